// round 14
// baseline (speedup 1.0000x reference)
#include <cuda_runtime.h>
#include <math.h>
#include <stdint.h>

#define DM   256
#define NH   8
#define DK   32
#define DFF  1024
#define NLAY 6
#define BB   8
#define LL   1024
#define TT   (BB * LL)     /* 8192 tokens */
#define TOPK 256
#define EPSF 1e-5f

/* ------------------------------------------------------------------ */
/* scratch (static device globals: no runtime allocation)             */
/* ------------------------------------------------------------------ */
__device__ float g_H[TT * DM];
__device__ float g_S[TT * DM];
__device__ float g_QKV[TT * 3 * DM];
__device__ float g_O[TT * DM];
__device__ float g_P[TT * DM];
__device__ float g_F[TT * DFF];
__device__ float g_VOL[BB * DFF];
/* transposed tf32 split of K (scale folded in): [bh][32 dims][1024 keys] */
__device__ unsigned g_KThi[BB * NH * DK * LL];
__device__ unsigned g_KTlo[BB * NH * DK * LL];
/* tf32 split of V, native layout: [bh][1024 keys][32 dims] */
__device__ unsigned g_Vhi[BB * NH * LL * DK];
__device__ unsigned g_Vlo[BB * NH * LL * DK];

/* ------------------------------------------------------------------ */
/* tf32 helpers (mapping validated by passing 3xTF32 GEMM)             */
/* ------------------------------------------------------------------ */
__device__ __forceinline__ unsigned cvt_tf32(float x) {
    unsigned r;
    asm("cvt.rna.tf32.f32 %0, %1;" : "=r"(r) : "f"(x));
    return r;
}
__device__ __forceinline__ void split_tf32(float x, unsigned& hi, unsigned& lo) {
    hi = cvt_tf32(x);
    lo = cvt_tf32(x - __uint_as_float(hi));
}
__device__ __forceinline__ void mma_tf32(float& d0, float& d1, float& d2, float& d3,
                                         unsigned a0, unsigned a1, unsigned a2, unsigned a3,
                                         unsigned b0, unsigned b1) {
    asm volatile(
        "mma.sync.aligned.m16n8k8.row.col.f32.tf32.tf32.f32 "
        "{%0,%1,%2,%3},{%4,%5,%6,%7},{%8,%9},{%0,%1,%2,%3};"
        : "+f"(d0), "+f"(d1), "+f"(d2), "+f"(d3)
        : "r"(a0), "r"(a1), "r"(a2), "r"(a3), "r"(b0), "r"(b1));
}

/* ------------------------------------------------------------------ */
/* embed: h = x @ in_w + in_b + PE                                     */
/* ------------------------------------------------------------------ */
__global__ void embed_kernel(const float* __restrict__ x,
                             const float* __restrict__ in_w,
                             const float* __restrict__ in_b) {
    int t = blockIdx.x;
    int d = threadIdx.x;
    int l = t & (LL - 1);
    const float c = -9.210340371976184f / 256.0f;  /* -ln(10000)/256 */
    float div = expf((float)(d & ~1) * c);
    float ang = (float)l * div;
    float pe = (d & 1) ? cosf(ang) : sinf(ang);
    g_H[(size_t)t * DM + d] =
        x[t * 2 + 0] * in_w[d] + x[t * 2 + 1] * in_w[DM + d] + in_b[d] + pe;
}

/* ------------------------------------------------------------------ */
/* LayerNorm: warp per token, 8 tokens per 256-thread block            */
/* ------------------------------------------------------------------ */
__device__ __forceinline__ void warp_reduce_2(float& s, float& q) {
#pragma unroll
    for (int o = 16; o > 0; o >>= 1) {
        s += __shfl_xor_sync(0xffffffffu, s, o);
        q += __shfl_xor_sync(0xffffffffu, q, o);
    }
}

__device__ __forceinline__ float4 ln_apply(float4 v, float mean, float r,
                                           float4 g, float4 b) {
    float4 o;
    o.x = (v.x - mean) * r * g.x + b.x;
    o.y = (v.y - mean) * r * g.y + b.y;
    o.z = (v.z - mean) * r * g.z + b.z;
    o.w = (v.w - mean) * r * g.w + b.w;
    return o;
}

/* dst = LN(src) */
__global__ void ln_kernel(const float* __restrict__ src,
                          const float* __restrict__ g,
                          const float* __restrict__ bt,
                          float* __restrict__ dst) {
    int w = threadIdx.x >> 5, lane = threadIdx.x & 31;
    size_t t = (size_t)blockIdx.x * 8 + w;
    const float4* s4 = (const float4*)(src + t * DM);
    float4 a = s4[lane * 2], b = s4[lane * 2 + 1];
    float s = a.x + a.y + a.z + a.w + b.x + b.y + b.z + b.w;
    float q = a.x*a.x + a.y*a.y + a.z*a.z + a.w*a.w
            + b.x*b.x + b.y*b.y + b.z*b.z + b.w*b.w;
    warp_reduce_2(s, q);
    float mean = s * (1.f / DM);
    float var  = q * (1.f / DM) - mean * mean;
    float r = rsqrtf(var + EPSF);
    float4 g0 = ((const float4*)g)[lane * 2], g1 = ((const float4*)g)[lane * 2 + 1];
    float4 b0 = ((const float4*)bt)[lane * 2], b1 = ((const float4*)bt)[lane * 2 + 1];
    float4* d4 = (float4*)(dst + t * DM);
    d4[lane * 2]     = ln_apply(a, mean, r, g0, b0);
    d4[lane * 2 + 1] = ln_apply(b, mean, r, g1, b1);
}

/* H += LN(P + S) */
__global__ void lna_kernel(const float* __restrict__ Pp,
                           const float* __restrict__ Sp,
                           const float* __restrict__ g,
                           const float* __restrict__ bt,
                           float* __restrict__ H) {
    int w = threadIdx.x >> 5, lane = threadIdx.x & 31;
    size_t t = (size_t)blockIdx.x * 8 + w;
    const float4* p4 = (const float4*)(Pp + t * DM);
    const float4* s4 = (const float4*)(Sp + t * DM);
    float4 pa = p4[lane * 2], pb = p4[lane * 2 + 1];
    float4 sa = s4[lane * 2], sb = s4[lane * 2 + 1];
    float4 a, b;
    a.x = pa.x + sa.x; a.y = pa.y + sa.y; a.z = pa.z + sa.z; a.w = pa.w + sa.w;
    b.x = pb.x + sb.x; b.y = pb.y + sb.y; b.z = pb.z + sb.z; b.w = pb.w + sb.w;
    float s = a.x + a.y + a.z + a.w + b.x + b.y + b.z + b.w;
    float q = a.x*a.x + a.y*a.y + a.z*a.z + a.w*a.w
            + b.x*b.x + b.y*b.y + b.z*b.z + b.w*b.w;
    warp_reduce_2(s, q);
    float mean = s * (1.f / DM);
    float var  = q * (1.f / DM) - mean * mean;
    float r = rsqrtf(var + EPSF);
    float4 g0 = ((const float4*)g)[lane * 2], g1 = ((const float4*)g)[lane * 2 + 1];
    float4 b0 = ((const float4*)bt)[lane * 2], b1 = ((const float4*)bt)[lane * 2 + 1];
    float4 r0 = ln_apply(a, mean, r, g0, b0);
    float4 r1 = ln_apply(b, mean, r, g1, b1);
    float4* h4 = (float4*)(H + t * DM);
    float4 h0 = h4[lane * 2], h1 = h4[lane * 2 + 1];
    h0.x += r0.x; h0.y += r0.y; h0.z += r0.z; h0.w += r0.w;
    h1.x += r1.x; h1.y += r1.y; h1.z += r1.z; h1.w += r1.w;
    h4[lane * 2]     = h0;
    h4[lane * 2 + 1] = h1;
}

/* ------------------------------------------------------------------ */
/* K/V preconvert: K -> tf32 hi/lo transposed (scale folded),          */
/*                 V -> tf32 hi/lo native layout                       */
/* ------------------------------------------------------------------ */
__global__ void kvconv_kernel() {
    __shared__ float tile[32][33];
    int bh = blockIdx.y;
    int kt = blockIdx.x;              /* 32 keys per tile */
    int b = bh >> 3, h = bh & 7;
    int t = threadIdx.x;
    size_t tok0 = (size_t)b * LL + kt * 32;
    {
        int kl = t >> 5, d = t & 31;
#pragma unroll
        for (int r = 0; r < 4; r++) {
            int key = kl + r * 8;
            tile[key][d] = g_QKV[(tok0 + key) * 768 + 256 + h * 32 + d];
        }
    }
    {
#pragma unroll
        for (int r = 0; r < 4; r++) {
            int idx = t + r * 256;
            int key = idx >> 5, d = idx & 31;
            float v = g_QKV[(tok0 + key) * 768 + 512 + h * 32 + d];
            unsigned hi, lo;
            split_tf32(v, hi, lo);
            size_t o = ((size_t)bh * LL + kt * 32 + key) * 32 + d;
            g_Vhi[o] = hi;
            g_Vlo[o] = lo;
        }
    }
    __syncthreads();
    {
        int dl = t >> 5, key = t & 31;
        const float scale = 0.17677669529663687f; /* 1/sqrt(32) */
#pragma unroll
        for (int r = 0; r < 4; r++) {
            int d2 = dl + r * 8;
            float v = tile[key][d2] * scale;
            unsigned hi, lo;
            split_tf32(v, hi, lo);
            size_t idx = ((size_t)bh * 32 + d2) * LL + kt * 32 + key;
            g_KThi[idx] = hi;
            g_KTlo[idx] = lo;
        }
    }
}

/* ------------------------------------------------------------------ */
/* 3xTF32 tensor-core GEMM: C[M,N] (=|+=) A[M,K] @ B[K,N] + bias       */
/* BM=128, BN=64, BK=16, 256 threads, warp tile 32x32 (m16n8k8 mma)    */
/* (R11 version — R13 prefetch reverted)                               */
/* ------------------------------------------------------------------ */
template <bool ADD, bool USEVOL>
__global__ void __launch_bounds__(256, 2)
gemm_kernel(const float* __restrict__ A,
            const float* __restrict__ Bw,
            const float* __restrict__ bias,
            float* __restrict__ C,
            int M, int N, int K) {
    __shared__ unsigned Abig[16][136], Asml[16][136];
    __shared__ unsigned Bbig[16][72],  Bsml[16][72];

    int tid = threadIdx.x;
    int lane = tid & 31, wid = tid >> 5;
    int g = lane >> 2, tg = lane & 3;
    int wm = (wid >> 1) * 32;
    int wn = (wid & 1) * 32;
    int bn0 = blockIdx.x * 64;
    int bm0 = blockIdx.y * 128;

    const float* volp = USEVOL ? (g_VOL + (size_t)((bm0 >> 10) << 10)) : (const float*)0;

    float acc[2][4][4];
#pragma unroll
    for (int mt = 0; mt < 2; mt++)
#pragma unroll
        for (int nt = 0; nt < 4; nt++)
#pragma unroll
            for (int i = 0; i < 4; i++) acc[mt][nt][i] = 0.f;

    int ar = tid >> 1, ac = (tid & 1) * 8;
    int br = tid >> 4, bc = (tid & 15) * 4;

    for (int k0 = 0; k0 < K; k0 += 16) {
        __syncthreads();
        {
            const float* ap = &A[(size_t)(bm0 + ar) * K + k0 + ac];
            float4 av0 = *(const float4*)ap;
            float4 av1 = *(const float4*)(ap + 4);
            if (USEVOL) {
                av0.x *= volp[k0 + ac + 0]; av0.y *= volp[k0 + ac + 1];
                av0.z *= volp[k0 + ac + 2]; av0.w *= volp[k0 + ac + 3];
                av1.x *= volp[k0 + ac + 4]; av1.y *= volp[k0 + ac + 5];
                av1.z *= volp[k0 + ac + 6]; av1.w *= volp[k0 + ac + 7];
            }
            float xs[8] = {av0.x, av0.y, av0.z, av0.w,
                           av1.x, av1.y, av1.z, av1.w};
#pragma unroll
            for (int j = 0; j < 8; j++) {
                unsigned hi, lo;
                split_tf32(xs[j], hi, lo);
                Abig[ac + j][ar] = hi;
                Asml[ac + j][ar] = lo;
            }
            const float* bp = &Bw[(size_t)(k0 + br) * N + bn0 + bc];
            float4 bv = *(const float4*)bp;
            uint4 hb, lb;
            split_tf32(bv.x, hb.x, lb.x);
            split_tf32(bv.y, hb.y, lb.y);
            split_tf32(bv.z, hb.z, lb.z);
            split_tf32(bv.w, hb.w, lb.w);
            *(uint4*)&Bbig[br][bc] = hb;
            *(uint4*)&Bsml[br][bc] = lb;
        }
        __syncthreads();

#pragma unroll
        for (int ks = 0; ks < 2; ks++) {
            int kb = ks * 8;
            unsigned ab[2][4], al[2][4];
#pragma unroll
            for (int mt = 0; mt < 2; mt++) {
                int m0 = wm + mt * 16 + g;
                ab[mt][0] = Abig[kb + tg    ][m0];
                ab[mt][1] = Abig[kb + tg    ][m0 + 8];
                ab[mt][2] = Abig[kb + tg + 4][m0];
                ab[mt][3] = Abig[kb + tg + 4][m0 + 8];
                al[mt][0] = Asml[kb + tg    ][m0];
                al[mt][1] = Asml[kb + tg    ][m0 + 8];
                al[mt][2] = Asml[kb + tg + 4][m0];
                al[mt][3] = Asml[kb + tg + 4][m0 + 8];
            }
            unsigned bb[4][2], bl[4][2];
#pragma unroll
            for (int nt = 0; nt < 4; nt++) {
                int n0 = wn + nt * 8 + g;
                bb[nt][0] = Bbig[kb + tg    ][n0];
                bb[nt][1] = Bbig[kb + tg + 4][n0];
                bl[nt][0] = Bsml[kb + tg    ][n0];
                bl[nt][1] = Bsml[kb + tg + 4][n0];
            }
#pragma unroll
            for (int mt = 0; mt < 2; mt++)
#pragma unroll
                for (int nt = 0; nt < 4; nt++) {
                    float* d = acc[mt][nt];
                    mma_tf32(d[0], d[1], d[2], d[3],
                             ab[mt][0], ab[mt][1], ab[mt][2], ab[mt][3],
                             bb[nt][0], bb[nt][1]);
                    mma_tf32(d[0], d[1], d[2], d[3],
                             al[mt][0], al[mt][1], al[mt][2], al[mt][3],
                             bb[nt][0], bb[nt][1]);
                    mma_tf32(d[0], d[1], d[2], d[3],
                             ab[mt][0], ab[mt][1], ab[mt][2], ab[mt][3],
                             bl[nt][0], bl[nt][1]);
                }
        }
    }

#pragma unroll
    for (int mt = 0; mt < 2; mt++)
#pragma unroll
        for (int nt = 0; nt < 4; nt++) {
            int r0 = bm0 + wm + mt * 16 + g;
            int c0 = bn0 + wn + nt * 8 + tg * 2;
            float2 bi = *(const float2*)&bias[c0];
            float* p0 = &C[(size_t)r0 * N + c0];
            float* p1 = &C[(size_t)(r0 + 8) * N + c0];
            float2 v0, v1;
            v0.x = acc[mt][nt][0] + bi.x; v0.y = acc[mt][nt][1] + bi.y;
            v1.x = acc[mt][nt][2] + bi.x; v1.y = acc[mt][nt][3] + bi.y;
            if (ADD) {
                float2 o0 = *(float2*)p0, o1 = *(float2*)p1;
                v0.x += o0.x; v0.y += o0.y;
                v1.x += o1.x; v1.y += o1.y;
            }
            *(float2*)p0 = v0;
            *(float2*)p1 = v1;
        }
}

/* ------------------------------------------------------------------ */
/* ProbSparse attention, 16 queries per 512-thread block               */
/* phase 1 (QK^T) and phase 3 (AV) on tensor cores (3xTF32)            */
/* phase 2: radix select with candidate compaction after pass 1        */
/* ------------------------------------------------------------------ */
#define SC_PITCH  1032
#define SC_OFF    0
#define HIST_OFF  16512
#define QHI_OFF   20608
#define QLO_OFF   21184
#define RZ_OFF    21760
#define CAND_OFF  21776
#define CNT_OFF   25872
#define ATTN_SMEM (25888 * 4)

__device__ __forceinline__ unsigned f2u(float f) {
    unsigned u = __float_as_uint(f);
    return (u & 0x80000000u) ? ~u : (u | 0x80000000u);
}
__device__ __forceinline__ float u2f(unsigned x) {
    unsigned v = (x & 0x80000000u) ? (x ^ 0x80000000u) : ~x;
    return __uint_as_float(v);
}

/* warp-parallel bin selection over 256-bin histogram (descending) */
__device__ __forceinline__ int radix_sel(const int* hw, int lane, int& krem) {
    int gs = 0;
#pragma unroll
    for (int i = 0; i < 8; i++) gs += hw[255 - (lane * 8 + i)];
    int S = gs;
#pragma unroll
    for (int off = 1; off < 32; off <<= 1) {
        int t2 = __shfl_up_sync(0xffffffffu, S, off);
        if (lane >= off) S += t2;
    }
    unsigned bal = __ballot_sync(0xffffffffu, S >= krem);
    int L = __ffs(bal) - 1;
    int SL  = __shfl_sync(0xffffffffu, S, L);
    int gsL = __shfl_sync(0xffffffffu, gs, L);
    int c = SL - gsL, selbin = 255 - L * 8, knew = krem;
#pragma unroll
    for (int i = 0; i < 8; i++) {
        int bn = 255 - (L * 8 + i);
        int hv = hw[bn];
        c += hv;
        if (c >= krem) { selbin = bn; knew = krem - (c - hv); break; }
    }
    krem = knew;
    return selbin;
}

__global__ void __launch_bounds__(512, 2)
attn_kernel(const float* __restrict__ QKV, float* __restrict__ O) {
    extern __shared__ float smx[];
    unsigned* scu  = (unsigned*)(smx + SC_OFF);   /* u32 scores -> fp32 weights */
    int*      histb = (int*)(smx + HIST_OFF);     /* later: AV partials */
    unsigned* Qhi  = (unsigned*)(smx + QHI_OFF);
    unsigned* Qlo  = (unsigned*)(smx + QLO_OFF);
    float*    rzs  = smx + RZ_OFF;
    unsigned* candb = (unsigned*)(smx + CAND_OFF);
    int*      cnts  = (int*)(smx + CNT_OFF);

    int tid = threadIdx.x, lane = tid & 31, w = tid >> 5;
    int bh = blockIdx.y, b = bh >> 3, h = bh & 7;
    int qbase = blockIdx.x * 16;
    size_t tokbase = (size_t)b * LL;
    const float* base = QKV + tokbase * 768 + h * 32;

    /* stage Q tile as tf32 hi/lo: 16 x 32, pitch 36 */
    {
        int q = tid >> 5, d = tid & 31;
        float qv = base[(size_t)(qbase + q) * 768 + d];
        unsigned hi, lo;
        split_tf32(qv, hi, lo);
        Qhi[q * 36 + d] = hi;
        Qlo[q * 36 + d] = lo;
    }
    __syncthreads();

    int g = lane >> 2, tg = lane & 3;

    /* ---------------- phase 1: S = Q K^T via 3xTF32 mma ------------- */
    {
        unsigned ah[4][4], al[4][4];
#pragma unroll
        for (int s = 0; s < 4; s++) {
            int d0 = s * 8;
            ah[s][0] = Qhi[g * 36 + d0 + tg];
            ah[s][1] = Qhi[(g + 8) * 36 + d0 + tg];
            ah[s][2] = Qhi[g * 36 + d0 + tg + 4];
            ah[s][3] = Qhi[(g + 8) * 36 + d0 + tg + 4];
            al[s][0] = Qlo[g * 36 + d0 + tg];
            al[s][1] = Qlo[(g + 8) * 36 + d0 + tg];
            al[s][2] = Qlo[g * 36 + d0 + tg + 4];
            al[s][3] = Qlo[(g + 8) * 36 + d0 + tg + 4];
        }
        const unsigned* KH = g_KThi + (size_t)bh * 32 * LL;
        const unsigned* KL = g_KTlo + (size_t)bh * 32 * LL;
        int off0 = tg * LL + g;
        int off1 = (tg + 4) * LL + g;
#pragma unroll
        for (int kg = 0; kg < 8; kg++) {
            int kb = w * 64 + kg * 8;
            float c0 = 0.f, c1 = 0.f, c2 = 0.f, c3 = 0.f;
#pragma unroll
            for (int s = 0; s < 4; s++) {
                unsigned b0h = KH[s * 8 * LL + kb + off0];
                unsigned b1h = KH[s * 8 * LL + kb + off1];
                unsigned b0l = KL[s * 8 * LL + kb + off0];
                unsigned b1l = KL[s * 8 * LL + kb + off1];
                mma_tf32(c0, c1, c2, c3,
                         ah[s][0], ah[s][1], ah[s][2], ah[s][3], b0h, b1h);
                mma_tf32(c0, c1, c2, c3,
                         al[s][0], al[s][1], al[s][2], al[s][3], b0h, b1h);
                mma_tf32(c0, c1, c2, c3,
                         ah[s][0], ah[s][1], ah[s][2], ah[s][3], b0l, b1l);
            }
            int cc = kb + tg * 2;
            uint2 p0 = make_uint2(f2u(c0), f2u(c1));
            uint2 p1 = make_uint2(f2u(c2), f2u(c3));
            *(uint2*)&scu[g * SC_PITCH + cc]       = p0;
            *(uint2*)&scu[(g + 8) * SC_PITCH + cc] = p1;
        }
    }
    __syncthreads();

    unsigned* row = scu + w * SC_PITCH;
    const uint4* row4 = (const uint4*)row;

    /* -------- phase 2: exact 256-th largest (radix + compaction) ---- */
    int* hw = histb + w * 256;
    unsigned* cand = candb + w * 256;
    unsigned prefix = 0, umax = 0;
    int krem = TOPK;

    /* pass 0: full scan on top byte (+umax) */
    for (int i = lane; i < 256; i += 32) hw[i] = 0;
    __syncwarp();
    for (int j4 = lane; j4 < 256; j4 += 32) {
        uint4 s4 = row4[j4];
        umax = max(max(umax, s4.x), max(s4.y, max(s4.z, s4.w)));
        atomicAdd(&hw[s4.x >> 24], 1);
        atomicAdd(&hw[s4.y >> 24], 1);
        atomicAdd(&hw[s4.z >> 24], 1);
        atomicAdd(&hw[s4.w >> 24], 1);
    }
    __syncwarp();
    prefix = ((unsigned)radix_sel(hw, lane, krem)) << 24;
    __syncwarp();

    /* pass 1: full scan on byte 2 among byte-3 matches */
    for (int i = lane; i < 256; i += 32) hw[i] = 0;
    __syncwarp();
    {
        unsigned b3 = prefix >> 24;
        for (int j4 = lane; j4 < 256; j4 += 32) {
            uint4 s4 = row4[j4];
            if ((s4.x >> 24) == b3) atomicAdd(&hw[(s4.x >> 16) & 255], 1);
            if ((s4.y >> 24) == b3) atomicAdd(&hw[(s4.y >> 16) & 255], 1);
            if ((s4.z >> 24) == b3) atomicAdd(&hw[(s4.z >> 16) & 255], 1);
            if ((s4.w >> 24) == b3) atomicAdd(&hw[(s4.w >> 16) & 255], 1);
        }
    }
    __syncwarp();
    prefix |= ((unsigned)radix_sel(hw, lane, krem)) << 16;
    int cnt1 = hw[(prefix >> 16) & 255];
    __syncwarp();

    unsigned pfx16 = prefix >> 16;
    if (cnt1 <= 256) {
        /* compact candidates matching the 16-bit prefix */
        if (lane == 0) cnts[w] = 0;
        __syncwarp();
        for (int j4 = lane; j4 < 256; j4 += 32) {
            uint4 s4 = row4[j4];
            if ((s4.x >> 16) == pfx16) cand[atomicAdd(&cnts[w], 1)] = s4.x;
            if ((s4.y >> 16) == pfx16) cand[atomicAdd(&cnts[w], 1)] = s4.y;
            if ((s4.z >> 16) == pfx16) cand[atomicAdd(&cnts[w], 1)] = s4.z;
            if ((s4.w >> 16) == pfx16) cand[atomicAdd(&cnts[w], 1)] = s4.w;
        }
        __syncwarp();
        int n = cnts[w];
        /* pass 2 over candidates */
        for (int i = lane; i < 256; i += 32) hw[i] = 0;
        __syncwarp();
        for (int i = lane; i < n; i += 32)
            atomicAdd(&hw[(cand[i] >> 8) & 255], 1);
        __syncwarp();
        prefix |= ((unsigned)radix_sel(hw, lane, krem)) << 8;
        __syncwarp();
        /* pass 3 over candidates */
        for (int i = lane; i < 256; i += 32) hw[i] = 0;
        __syncwarp();
        {
            unsigned pfx24 = prefix >> 8;
            for (int i = lane; i < n; i += 32) {
                unsigned u = cand[i];
                if ((u >> 8) == pfx24) atomicAdd(&hw[u & 255], 1);
            }
        }
        __syncwarp();
        prefix |= (unsigned)radix_sel(hw, lane, krem);
    } else {
        /* fallback: full scans for passes 2,3 (exact, rare) */
#pragma unroll
        for (int pass = 2; pass < 4; pass++) {
            int shift = 24 - 8 * pass;
            for (int i = lane; i < 256; i += 32) hw[i] = 0;
            __syncwarp();
            for (int j4 = lane; j4 < 256; j4 += 32) {
                uint4 s4 = row4[j4];
                unsigned hi = (prefix >> shift) >> 8;
                if (((s4.x >> shift) >> 8) == hi) atomicAdd(&hw[(s4.x >> shift) & 255], 1);
                if (((s4.y >> shift) >> 8) == hi) atomicAdd(&hw[(s4.y >> shift) & 255], 1);
                if (((s4.z >> shift) >> 8) == hi) atomicAdd(&hw[(s4.z >> shift) & 255], 1);
                if (((s4.w >> shift) >> 8) == hi) atomicAdd(&hw[(s4.w >> shift) & 255], 1);
            }
            __syncwarp();
            prefix |= ((unsigned)radix_sel(hw, lane, krem)) << shift;
            __syncwarp();
        }
    }
#pragma unroll
    for (int o = 16; o > 0; o >>= 1)
        umax = max(umax, __shfl_xor_sync(0xffffffffu, umax, o));
    float lmax = u2f(umax);
    unsigned thr = prefix;

    /* -------- softmax: dense weights written back over score row ---- */
    float zs = 0.f;
#pragma unroll
    for (int kt = 0; kt < 8; kt++) {
        uint4 s4 = row4[kt * 32 + lane];
        float w0 = (s4.x >= thr) ? __expf(u2f(s4.x) - lmax) : 0.f;
        float w1 = (s4.y >= thr) ? __expf(u2f(s4.y) - lmax) : 0.f;
        float w2 = (s4.z >= thr) ? __expf(u2f(s4.z) - lmax) : 0.f;
        float w3 = (s4.w >= thr) ? __expf(u2f(s4.w) - lmax) : 0.f;
        ((float4*)row)[kt * 32 + lane] = make_float4(w0, w1, w2, w3);
        zs += w0 + w1 + w2 + w3;
    }
#pragma unroll
    for (int o = 16; o > 0; o >>= 1) zs += __shfl_xor_sync(0xffffffffu, zs, o);
    if (lane == 0) rzs[w] = 1.f / zs;
    __syncthreads();   /* all weights + rz visible to all warps */

    /* -------- phase 3: O = W @ V via 3xTF32 mma (dense) ------------- */
    float av[4][4];
#pragma unroll
    for (int nt = 0; nt < 4; nt++)
#pragma unroll
        for (int i = 0; i < 4; i++) av[nt][i] = 0.f;
    {
        const float* scwf = (const float*)scu;
        const unsigned* VH = g_Vhi + ((size_t)bh * LL + w * 64) * 32;
        const unsigned* VL = g_Vlo + ((size_t)bh * LL + w * 64) * 32;
#pragma unroll
        for (int s = 0; s < 8; s++) {
            int k = w * 64 + s * 8;
            float w00 = scwf[g * SC_PITCH + k + tg];
            float w10 = scwf[(g + 8) * SC_PITCH + k + tg];
            float w01 = scwf[g * SC_PITCH + k + tg + 4];
            float w11 = scwf[(g + 8) * SC_PITCH + k + tg + 4];
            unsigned a0h, a0l, a1h, a1l, a2h, a2l, a3h, a3l;
            split_tf32(w00, a0h, a0l);
            split_tf32(w10, a1h, a1l);
            split_tf32(w01, a2h, a2l);
            split_tf32(w11, a3h, a3l);
            int r0 = (s * 8 + tg) * 32;
            int r1 = (s * 8 + tg + 4) * 32;
#pragma unroll
            for (int nt = 0; nt < 4; nt++) {
                int c = nt * 8 + g;
                unsigned b0h = VH[r0 + c], b1h = VH[r1 + c];
                unsigned b0l = VL[r0 + c], b1l = VL[r1 + c];
                float* d = av[nt];
                mma_tf32(d[0], d[1], d[2], d[3], a0h, a1h, a2h, a3h, b0h, b1h);
                mma_tf32(d[0], d[1], d[2], d[3], a0l, a1l, a2l, a3l, b0h, b1h);
                mma_tf32(d[0], d[1], d[2], d[3], a0h, a1h, a2h, a3h, b0l, b1l);
            }
        }
    }

    /* -------- cross-warp reduction of AV partials (2 d-halves) ------ */
    float* P = smx + HIST_OFF;   /* 4096 floats; hist is dead */
#pragma unroll
    for (int hh = 0; hh < 2; hh++) {
        __syncthreads();
#pragma unroll
        for (int nt = hh * 2; nt < hh * 2 + 2; nt++) {
            int dl = (nt - hh * 2) * 8 + tg * 2;
            P[w * 256 + g * 16 + dl]           = av[nt][0];
            P[w * 256 + g * 16 + dl + 1]       = av[nt][1];
            P[w * 256 + (g + 8) * 16 + dl]     = av[nt][2];
            P[w * 256 + (g + 8) * 16 + dl + 1] = av[nt][3];
        }
        __syncthreads();
        if (tid < 256) {
            int q = tid >> 4, dl = tid & 15;
            float s = 0.f;
#pragma unroll
            for (int w2 = 0; w2 < 16; w2++) s += P[w2 * 256 + q * 16 + dl];
            O[(tokbase + qbase + q) * 256 + h * 32 + hh * 16 + dl] = s * rzs[q];
        }
    }
}

/* ------------------------------------------------------------------ */
/* Volatilite: vol[b,j] = std over L of F[b,:,j]                       */
/* ------------------------------------------------------------------ */
__global__ void vol_kernel(const float* __restrict__ F) {
    int tx = threadIdx.x & 127;
    int ty = threadIdx.x >> 7;
    int j = blockIdx.x * 128 + tx;
    int b = blockIdx.y;
    float s = 0.f, ss = 0.f;
    for (int l = ty; l < LL; l += 4) {
        float v = F[((size_t)(b * LL + l)) * DFF + j];
        s += v; ss += v * v;
    }
    __shared__ float sh1[4][128], sh2[4][128];
    sh1[ty][tx] = s; sh2[ty][tx] = ss;
    __syncthreads();
    if (ty == 0) {
        s  = sh1[0][tx] + sh1[1][tx] + sh1[2][tx] + sh1[3][tx];
        ss = sh2[0][tx] + sh2[1][tx] + sh2[2][tx] + sh2[3][tx];
        float mean = s * (1.f / LL);
        float var  = ss * (1.f / LL) - mean * mean;
        g_VOL[b * DFF + j] = sqrtf(fmaxf(var, 0.f));
    }
}

/* ------------------------------------------------------------------ */
extern "C" void kernel_launch(void* const* d_in, const int* in_sizes, int n_in,
                              void* d_out, int out_size) {
    const float* x     = (const float*)d_in[0];
    const float* in_w  = (const float*)d_in[1];
    const float* in_b  = (const float*)d_in[2];
    const float* ln1_g = (const float*)d_in[3];
    const float* ln1_b = (const float*)d_in[4];
    const float* qkv_w = (const float*)d_in[5];
    const float* qkv_b = (const float*)d_in[6];
    const float* out_w = (const float*)d_in[7];
    const float* out_b = (const float*)d_in[8];
    const float* lna_g = (const float*)d_in[9];
    const float* lna_b = (const float*)d_in[10];
    const float* ln2_g = (const float*)d_in[11];
    const float* ln2_b = (const float*)d_in[12];
    const float* ff1_w = (const float*)d_in[13];
    const float* ff1_b = (const float*)d_in[14];
    const float* ff2_w = (const float*)d_in[15];
    const float* ff2_b = (const float*)d_in[16];
    const float* lnf_g = (const float*)d_in[17];
    const float* lnf_b = (const float*)d_in[18];
    float* out = (float*)d_out;

    float *H, *S, *Q, *O, *P, *F;
    cudaGetSymbolAddress((void**)&H, g_H);
    cudaGetSymbolAddress((void**)&S, g_S);
    cudaGetSymbolAddress((void**)&Q, g_QKV);
    cudaGetSymbolAddress((void**)&O, g_O);
    cudaGetSymbolAddress((void**)&P, g_P);
    cudaGetSymbolAddress((void**)&F, g_F);

    cudaFuncSetAttribute((const void*)attn_kernel,
                         cudaFuncAttributeMaxDynamicSharedMemorySize, ATTN_SMEM);

    embed_kernel<<<TT, 256>>>(x, in_w, in_b);

    for (int layer = 0; layer < NLAY; layer++) {
        /* s2 = LN1(h) */
        ln_kernel<<<TT / 8, 256>>>(H, ln1_g, ln1_b, S);
        /* qkv = s2 @ qkv_w + qkv_b */
        gemm_kernel<false, false><<<dim3(768 / 64, TT / 128), 256>>>(
            S, qkv_w, qkv_b, Q, TT, 768, DM);
        /* K -> tf32 hi/lo transposed, V -> tf32 hi/lo native */
        kvconv_kernel<<<dim3(32, BB * NH), 256>>>();
        /* probsparse attention */
        attn_kernel<<<dim3(LL / 16, BB * NH), 512, ATTN_SMEM>>>(Q, O);
        /* P = O @ out_w + out_b */
        gemm_kernel<false, false><<<dim3(256 / 64, TT / 128), 256>>>(
            O, out_w, out_b, P, TT, DM, DM);
        /* h += LN(P + s2) */
        lna_kernel<<<TT / 8, 256>>>(P, S, lna_g, lna_b, H);
        /* s2 = LN2(h) */
        ln_kernel<<<TT / 8, 256>>>(H, ln2_g, ln2_b, S);
        /* F = s2 @ ff1_w + ff1_b */
        gemm_kernel<false, false><<<dim3(1024 / 64, TT / 128), 256>>>(
            S, ff1_w, ff1_b, F, TT, DFF, DM);
        /* vol[b,j] */
        vol_kernel<<<dim3(DFF / 128, BB), 512>>>(F);
        /* h += (F * vol) @ ff2_w + ff2_b */
        gemm_kernel<true, true><<<dim3(256 / 64, TT / 128), 256>>>(
            F, ff2_w, ff2_b, H, TT, DM, DFF);
    }

    /* out = LN_f(h) */
    ln_kernel<<<TT / 8, 256>>>(H, lnf_g, lnf_b, out);
}

// round 15
// speedup vs baseline: 1.0470x; 1.0470x over previous
#include <cuda_runtime.h>
#include <math.h>
#include <stdint.h>

#define DM   256
#define NH   8
#define DK   32
#define DFF  1024
#define NLAY 6
#define BB   8
#define LL   1024
#define TT   (BB * LL)     /* 8192 tokens */
#define TOPK 256
#define EPSF 1e-5f

/* ------------------------------------------------------------------ */
/* scratch (static device globals: no runtime allocation)             */
/* ------------------------------------------------------------------ */
__device__ float g_H[TT * DM];
__device__ float g_S[TT * DM];
__device__ float g_QKV[TT * 3 * DM];
__device__ float g_O[TT * DM];
__device__ float g_P[TT * DM];
__device__ float g_F[TT * DFF];
__device__ float g_VOL[BB * DFF];
/* transposed tf32 split of K (scale folded in): [bh][32 dims][1024 keys] */
__device__ unsigned g_KThi[BB * NH * DK * LL];
__device__ unsigned g_KTlo[BB * NH * DK * LL];
/* tf32 split of V, native layout: [bh][1024 keys][32 dims] */
__device__ unsigned g_Vhi[BB * NH * LL * DK];
__device__ unsigned g_Vlo[BB * NH * LL * DK];

/* ------------------------------------------------------------------ */
/* tf32 helpers (mapping validated by passing 3xTF32 GEMM)             */
/* ------------------------------------------------------------------ */
__device__ __forceinline__ unsigned cvt_tf32(float x) {
    unsigned r;
    asm("cvt.rna.tf32.f32 %0, %1;" : "=r"(r) : "f"(x));
    return r;
}
__device__ __forceinline__ void split_tf32(float x, unsigned& hi, unsigned& lo) {
    hi = cvt_tf32(x);
    lo = cvt_tf32(x - __uint_as_float(hi));
}
__device__ __forceinline__ void mma_tf32(float& d0, float& d1, float& d2, float& d3,
                                         unsigned a0, unsigned a1, unsigned a2, unsigned a3,
                                         unsigned b0, unsigned b1) {
    asm volatile(
        "mma.sync.aligned.m16n8k8.row.col.f32.tf32.tf32.f32 "
        "{%0,%1,%2,%3},{%4,%5,%6,%7},{%8,%9},{%0,%1,%2,%3};"
        : "+f"(d0), "+f"(d1), "+f"(d2), "+f"(d3)
        : "r"(a0), "r"(a1), "r"(a2), "r"(a3), "r"(b0), "r"(b1));
}

/* ------------------------------------------------------------------ */
/* embed: h = x @ in_w + in_b + PE                                     */
/* ------------------------------------------------------------------ */
__global__ void embed_kernel(const float* __restrict__ x,
                             const float* __restrict__ in_w,
                             const float* __restrict__ in_b) {
    int t = blockIdx.x;
    int d = threadIdx.x;
    int l = t & (LL - 1);
    const float c = -9.210340371976184f / 256.0f;  /* -ln(10000)/256 */
    float div = expf((float)(d & ~1) * c);
    float ang = (float)l * div;
    float pe = (d & 1) ? cosf(ang) : sinf(ang);
    g_H[(size_t)t * DM + d] =
        x[t * 2 + 0] * in_w[d] + x[t * 2 + 1] * in_w[DM + d] + in_b[d] + pe;
}

/* ------------------------------------------------------------------ */
/* LayerNorm: warp per token, 8 tokens per 256-thread block            */
/* ------------------------------------------------------------------ */
__device__ __forceinline__ void warp_reduce_2(float& s, float& q) {
#pragma unroll
    for (int o = 16; o > 0; o >>= 1) {
        s += __shfl_xor_sync(0xffffffffu, s, o);
        q += __shfl_xor_sync(0xffffffffu, q, o);
    }
}

__device__ __forceinline__ float4 ln_apply(float4 v, float mean, float r,
                                           float4 g, float4 b) {
    float4 o;
    o.x = (v.x - mean) * r * g.x + b.x;
    o.y = (v.y - mean) * r * g.y + b.y;
    o.z = (v.z - mean) * r * g.z + b.z;
    o.w = (v.w - mean) * r * g.w + b.w;
    return o;
}

/* dst = LN(src) */
__global__ void ln_kernel(const float* __restrict__ src,
                          const float* __restrict__ g,
                          const float* __restrict__ bt,
                          float* __restrict__ dst) {
    int w = threadIdx.x >> 5, lane = threadIdx.x & 31;
    size_t t = (size_t)blockIdx.x * 8 + w;
    const float4* s4 = (const float4*)(src + t * DM);
    float4 a = s4[lane * 2], b = s4[lane * 2 + 1];
    float s = a.x + a.y + a.z + a.w + b.x + b.y + b.z + b.w;
    float q = a.x*a.x + a.y*a.y + a.z*a.z + a.w*a.w
            + b.x*b.x + b.y*b.y + b.z*b.z + b.w*b.w;
    warp_reduce_2(s, q);
    float mean = s * (1.f / DM);
    float var  = q * (1.f / DM) - mean * mean;
    float r = rsqrtf(var + EPSF);
    float4 g0 = ((const float4*)g)[lane * 2], g1 = ((const float4*)g)[lane * 2 + 1];
    float4 b0 = ((const float4*)bt)[lane * 2], b1 = ((const float4*)bt)[lane * 2 + 1];
    float4* d4 = (float4*)(dst + t * DM);
    d4[lane * 2]     = ln_apply(a, mean, r, g0, b0);
    d4[lane * 2 + 1] = ln_apply(b, mean, r, g1, b1);
}

/* fused: H += LN_a(P + S);  S = LN2(H)                                */
__global__ void lna_ln2_kernel(const float* __restrict__ Pp,
                               float* __restrict__ Sp,
                               const float* __restrict__ ga,
                               const float* __restrict__ ba,
                               const float* __restrict__ g2,
                               const float* __restrict__ b2,
                               float* __restrict__ H) {
    int w = threadIdx.x >> 5, lane = threadIdx.x & 31;
    size_t t = (size_t)blockIdx.x * 8 + w;
    const float4* p4 = (const float4*)(Pp + t * DM);
    const float4* s4 = (const float4*)(Sp + t * DM);
    float4 pa = p4[lane * 2], pb = p4[lane * 2 + 1];
    float4 sa = s4[lane * 2], sb = s4[lane * 2 + 1];
    float4 a, b;
    a.x = pa.x + sa.x; a.y = pa.y + sa.y; a.z = pa.z + sa.z; a.w = pa.w + sa.w;
    b.x = pb.x + sb.x; b.y = pb.y + sb.y; b.z = pb.z + sb.z; b.w = pb.w + sb.w;
    float s = a.x + a.y + a.z + a.w + b.x + b.y + b.z + b.w;
    float q = a.x*a.x + a.y*a.y + a.z*a.z + a.w*a.w
            + b.x*b.x + b.y*b.y + b.z*b.z + b.w*b.w;
    warp_reduce_2(s, q);
    float mean = s * (1.f / DM);
    float var  = q * (1.f / DM) - mean * mean;
    float r = rsqrtf(var + EPSF);
    float4 g0 = ((const float4*)ga)[lane * 2], g1 = ((const float4*)ga)[lane * 2 + 1];
    float4 c0 = ((const float4*)ba)[lane * 2], c1 = ((const float4*)ba)[lane * 2 + 1];
    float4 r0 = ln_apply(a, mean, r, g0, c0);
    float4 r1 = ln_apply(b, mean, r, g1, c1);
    /* h' = H + LN_a(P+S) */
    float4* h4 = (float4*)(H + t * DM);
    float4 h0 = h4[lane * 2], h1 = h4[lane * 2 + 1];
    h0.x += r0.x; h0.y += r0.y; h0.z += r0.z; h0.w += r0.w;
    h1.x += r1.x; h1.y += r1.y; h1.z += r1.z; h1.w += r1.w;
    h4[lane * 2]     = h0;
    h4[lane * 2 + 1] = h1;
    /* S = LN2(h') computed from registers */
    float s2 = h0.x + h0.y + h0.z + h0.w + h1.x + h1.y + h1.z + h1.w;
    float q2 = h0.x*h0.x + h0.y*h0.y + h0.z*h0.z + h0.w*h0.w
             + h1.x*h1.x + h1.y*h1.y + h1.z*h1.z + h1.w*h1.w;
    warp_reduce_2(s2, q2);
    float mean2 = s2 * (1.f / DM);
    float var2  = q2 * (1.f / DM) - mean2 * mean2;
    float r2 = rsqrtf(var2 + EPSF);
    float4 g20 = ((const float4*)g2)[lane * 2], g21 = ((const float4*)g2)[lane * 2 + 1];
    float4 b20 = ((const float4*)b2)[lane * 2], b21 = ((const float4*)b2)[lane * 2 + 1];
    float4* d4 = (float4*)(Sp + t * DM);
    d4[lane * 2]     = ln_apply(h0, mean2, r2, g20, b20);
    d4[lane * 2 + 1] = ln_apply(h1, mean2, r2, g21, b21);
}

/* ------------------------------------------------------------------ */
/* K/V preconvert: K -> tf32 hi/lo transposed (scale folded),          */
/*                 V -> tf32 hi/lo native layout                       */
/* ------------------------------------------------------------------ */
__global__ void kvconv_kernel() {
    __shared__ float tile[32][33];
    int bh = blockIdx.y;
    int kt = blockIdx.x;              /* 32 keys per tile */
    int b = bh >> 3, h = bh & 7;
    int t = threadIdx.x;
    size_t tok0 = (size_t)b * LL + kt * 32;
    {
        int kl = t >> 5, d = t & 31;
#pragma unroll
        for (int r = 0; r < 4; r++) {
            int key = kl + r * 8;
            tile[key][d] = g_QKV[(tok0 + key) * 768 + 256 + h * 32 + d];
        }
    }
    {
#pragma unroll
        for (int r = 0; r < 4; r++) {
            int idx = t + r * 256;
            int key = idx >> 5, d = idx & 31;
            float v = g_QKV[(tok0 + key) * 768 + 512 + h * 32 + d];
            unsigned hi, lo;
            split_tf32(v, hi, lo);
            size_t o = ((size_t)bh * LL + kt * 32 + key) * 32 + d;
            g_Vhi[o] = hi;
            g_Vlo[o] = lo;
        }
    }
    __syncthreads();
    {
        int dl = t >> 5, key = t & 31;
        const float scale = 0.17677669529663687f; /* 1/sqrt(32) */
#pragma unroll
        for (int r = 0; r < 4; r++) {
            int d2 = dl + r * 8;
            float v = tile[key][d2] * scale;
            unsigned hi, lo;
            split_tf32(v, hi, lo);
            size_t idx = ((size_t)bh * 32 + d2) * LL + kt * 32 + key;
            g_KThi[idx] = hi;
            g_KTlo[idx] = lo;
        }
    }
}

/* ------------------------------------------------------------------ */
/* 3xTF32 tensor-core GEMM: C[M,N] (=|+=) A[M,K] @ B[K,N] + bias       */
/* BM=128, BN=64, BK=16, 256 threads, warp tile 32x32 (m16n8k8 mma)    */
/* (exact R11 version)                                                 */
/* ------------------------------------------------------------------ */
template <bool ADD, bool USEVOL>
__global__ void __launch_bounds__(256, 2)
gemm_kernel(const float* __restrict__ A,
            const float* __restrict__ Bw,
            const float* __restrict__ bias,
            float* __restrict__ C,
            int M, int N, int K) {
    __shared__ unsigned Abig[16][136], Asml[16][136];
    __shared__ unsigned Bbig[16][72],  Bsml[16][72];

    int tid = threadIdx.x;
    int lane = tid & 31, wid = tid >> 5;
    int g = lane >> 2, tg = lane & 3;
    int wm = (wid >> 1) * 32;
    int wn = (wid & 1) * 32;
    int bn0 = blockIdx.x * 64;
    int bm0 = blockIdx.y * 128;

    const float* volp = USEVOL ? (g_VOL + (size_t)((bm0 >> 10) << 10)) : (const float*)0;

    float acc[2][4][4];
#pragma unroll
    for (int mt = 0; mt < 2; mt++)
#pragma unroll
        for (int nt = 0; nt < 4; nt++)
#pragma unroll
            for (int i = 0; i < 4; i++) acc[mt][nt][i] = 0.f;

    int ar = tid >> 1, ac = (tid & 1) * 8;
    int br = tid >> 4, bc = (tid & 15) * 4;

    for (int k0 = 0; k0 < K; k0 += 16) {
        __syncthreads();
        {
            const float* ap = &A[(size_t)(bm0 + ar) * K + k0 + ac];
            float4 av0 = *(const float4*)ap;
            float4 av1 = *(const float4*)(ap + 4);
            if (USEVOL) {
                av0.x *= volp[k0 + ac + 0]; av0.y *= volp[k0 + ac + 1];
                av0.z *= volp[k0 + ac + 2]; av0.w *= volp[k0 + ac + 3];
                av1.x *= volp[k0 + ac + 4]; av1.y *= volp[k0 + ac + 5];
                av1.z *= volp[k0 + ac + 6]; av1.w *= volp[k0 + ac + 7];
            }
            float xs[8] = {av0.x, av0.y, av0.z, av0.w,
                           av1.x, av1.y, av1.z, av1.w};
#pragma unroll
            for (int j = 0; j < 8; j++) {
                unsigned hi, lo;
                split_tf32(xs[j], hi, lo);
                Abig[ac + j][ar] = hi;
                Asml[ac + j][ar] = lo;
            }
            const float* bp = &Bw[(size_t)(k0 + br) * N + bn0 + bc];
            float4 bv = *(const float4*)bp;
            uint4 hb, lb;
            split_tf32(bv.x, hb.x, lb.x);
            split_tf32(bv.y, hb.y, lb.y);
            split_tf32(bv.z, hb.z, lb.z);
            split_tf32(bv.w, hb.w, lb.w);
            *(uint4*)&Bbig[br][bc] = hb;
            *(uint4*)&Bsml[br][bc] = lb;
        }
        __syncthreads();

#pragma unroll
        for (int ks = 0; ks < 2; ks++) {
            int kb = ks * 8;
            unsigned ab[2][4], al[2][4];
#pragma unroll
            for (int mt = 0; mt < 2; mt++) {
                int m0 = wm + mt * 16 + g;
                ab[mt][0] = Abig[kb + tg    ][m0];
                ab[mt][1] = Abig[kb + tg    ][m0 + 8];
                ab[mt][2] = Abig[kb + tg + 4][m0];
                ab[mt][3] = Abig[kb + tg + 4][m0 + 8];
                al[mt][0] = Asml[kb + tg    ][m0];
                al[mt][1] = Asml[kb + tg    ][m0 + 8];
                al[mt][2] = Asml[kb + tg + 4][m0];
                al[mt][3] = Asml[kb + tg + 4][m0 + 8];
            }
            unsigned bb[4][2], bl[4][2];
#pragma unroll
            for (int nt = 0; nt < 4; nt++) {
                int n0 = wn + nt * 8 + g;
                bb[nt][0] = Bbig[kb + tg    ][n0];
                bb[nt][1] = Bbig[kb + tg + 4][n0];
                bl[nt][0] = Bsml[kb + tg    ][n0];
                bl[nt][1] = Bsml[kb + tg + 4][n0];
            }
#pragma unroll
            for (int mt = 0; mt < 2; mt++)
#pragma unroll
                for (int nt = 0; nt < 4; nt++) {
                    float* d = acc[mt][nt];
                    mma_tf32(d[0], d[1], d[2], d[3],
                             ab[mt][0], ab[mt][1], ab[mt][2], ab[mt][3],
                             bb[nt][0], bb[nt][1]);
                    mma_tf32(d[0], d[1], d[2], d[3],
                             al[mt][0], al[mt][1], al[mt][2], al[mt][3],
                             bb[nt][0], bb[nt][1]);
                    mma_tf32(d[0], d[1], d[2], d[3],
                             ab[mt][0], ab[mt][1], ab[mt][2], ab[mt][3],
                             bl[nt][0], bl[nt][1]);
                }
        }
    }

#pragma unroll
    for (int mt = 0; mt < 2; mt++)
#pragma unroll
        for (int nt = 0; nt < 4; nt++) {
            int r0 = bm0 + wm + mt * 16 + g;
            int c0 = bn0 + wn + nt * 8 + tg * 2;
            float2 bi = *(const float2*)&bias[c0];
            float* p0 = &C[(size_t)r0 * N + c0];
            float* p1 = &C[(size_t)(r0 + 8) * N + c0];
            float2 v0, v1;
            v0.x = acc[mt][nt][0] + bi.x; v0.y = acc[mt][nt][1] + bi.y;
            v1.x = acc[mt][nt][2] + bi.x; v1.y = acc[mt][nt][3] + bi.y;
            if (ADD) {
                float2 o0 = *(float2*)p0, o1 = *(float2*)p1;
                v0.x += o0.x; v0.y += o0.y;
                v1.x += o1.x; v1.y += o1.y;
            }
            *(float2*)p0 = v0;
            *(float2*)p1 = v1;
        }
}

/* ------------------------------------------------------------------ */
/* ProbSparse attention, 16 queries per 512-thread block               */
/* phase 1 (QK^T) and phase 3 (AV) on tensor cores (3xTF32)            */
/* (exact R11 version)                                                 */
/* ------------------------------------------------------------------ */
#define SC_PITCH  1032
#define SC_OFF    0
#define HIST_OFF  16512
#define QHI_OFF   20608
#define QLO_OFF   21184
#define RZ_OFF    21760
#define ATTN_SMEM (21776 * 4)

__device__ __forceinline__ unsigned f2u(float f) {
    unsigned u = __float_as_uint(f);
    return (u & 0x80000000u) ? ~u : (u | 0x80000000u);
}
__device__ __forceinline__ float u2f(unsigned x) {
    unsigned v = (x & 0x80000000u) ? (x ^ 0x80000000u) : ~x;
    return __uint_as_float(v);
}

__global__ void __launch_bounds__(512, 2)
attn_kernel(const float* __restrict__ QKV, float* __restrict__ O) {
    extern __shared__ float smx[];
    unsigned* scu  = (unsigned*)(smx + SC_OFF);   /* u32 scores -> fp32 weights */
    int*      histb = (int*)(smx + HIST_OFF);     /* later: AV partials */
    unsigned* Qhi  = (unsigned*)(smx + QHI_OFF);
    unsigned* Qlo  = (unsigned*)(smx + QLO_OFF);
    float*    rzs  = smx + RZ_OFF;

    int tid = threadIdx.x, lane = tid & 31, w = tid >> 5;
    int bh = blockIdx.y, b = bh >> 3, h = bh & 7;
    int qbase = blockIdx.x * 16;
    size_t tokbase = (size_t)b * LL;
    const float* base = QKV + tokbase * 768 + h * 32;

    /* stage Q tile as tf32 hi/lo: 16 x 32, pitch 36 */
    {
        int q = tid >> 5, d = tid & 31;
        float qv = base[(size_t)(qbase + q) * 768 + d];
        unsigned hi, lo;
        split_tf32(qv, hi, lo);
        Qhi[q * 36 + d] = hi;
        Qlo[q * 36 + d] = lo;
    }
    __syncthreads();

    int g = lane >> 2, tg = lane & 3;

    /* ---------------- phase 1: S = Q K^T via 3xTF32 mma ------------- */
    {
        unsigned ah[4][4], al[4][4];
#pragma unroll
        for (int s = 0; s < 4; s++) {
            int d0 = s * 8;
            ah[s][0] = Qhi[g * 36 + d0 + tg];
            ah[s][1] = Qhi[(g + 8) * 36 + d0 + tg];
            ah[s][2] = Qhi[g * 36 + d0 + tg + 4];
            ah[s][3] = Qhi[(g + 8) * 36 + d0 + tg + 4];
            al[s][0] = Qlo[g * 36 + d0 + tg];
            al[s][1] = Qlo[(g + 8) * 36 + d0 + tg];
            al[s][2] = Qlo[g * 36 + d0 + tg + 4];
            al[s][3] = Qlo[(g + 8) * 36 + d0 + tg + 4];
        }
        const unsigned* KH = g_KThi + (size_t)bh * 32 * LL;
        const unsigned* KL = g_KTlo + (size_t)bh * 32 * LL;
        int off0 = tg * LL + g;
        int off1 = (tg + 4) * LL + g;
#pragma unroll
        for (int kg = 0; kg < 8; kg++) {
            int kb = w * 64 + kg * 8;
            float c0 = 0.f, c1 = 0.f, c2 = 0.f, c3 = 0.f;
#pragma unroll
            for (int s = 0; s < 4; s++) {
                unsigned b0h = KH[s * 8 * LL + kb + off0];
                unsigned b1h = KH[s * 8 * LL + kb + off1];
                unsigned b0l = KL[s * 8 * LL + kb + off0];
                unsigned b1l = KL[s * 8 * LL + kb + off1];
                mma_tf32(c0, c1, c2, c3,
                         ah[s][0], ah[s][1], ah[s][2], ah[s][3], b0h, b1h);
                mma_tf32(c0, c1, c2, c3,
                         al[s][0], al[s][1], al[s][2], al[s][3], b0h, b1h);
                mma_tf32(c0, c1, c2, c3,
                         ah[s][0], ah[s][1], ah[s][2], ah[s][3], b0l, b1l);
            }
            int cc = kb + tg * 2;
            uint2 p0 = make_uint2(f2u(c0), f2u(c1));
            uint2 p1 = make_uint2(f2u(c2), f2u(c3));
            *(uint2*)&scu[g * SC_PITCH + cc]       = p0;
            *(uint2*)&scu[(g + 8) * SC_PITCH + cc] = p1;
        }
    }
    __syncthreads();

    unsigned* row = scu + w * SC_PITCH;
    const uint4* row4 = (const uint4*)row;

    /* -------- phase 2: exact 256-th largest (4-pass radix, u32) ----- */
    int* hw = histb + w * 256;
    unsigned prefix = 0, umax = 0;
    int krem = TOPK;
#pragma unroll
    for (int pass = 0; pass < 4; pass++) {
        int shift = 24 - 8 * pass;
        for (int i = lane; i < 256; i += 32) hw[i] = 0;
        __syncwarp();
        for (int j4 = lane; j4 < 256; j4 += 32) {
            uint4 s4 = row4[j4];
            if (pass == 0) {
                umax = max(max(umax, s4.x), max(s4.y, max(s4.z, s4.w)));
                atomicAdd(&hw[s4.x >> 24], 1);
                atomicAdd(&hw[s4.y >> 24], 1);
                atomicAdd(&hw[s4.z >> 24], 1);
                atomicAdd(&hw[s4.w >> 24], 1);
            } else {
                unsigned hi = (prefix >> shift) >> 8;
                if (((s4.x >> shift) >> 8) == hi) atomicAdd(&hw[(s4.x >> shift) & 255], 1);
                if (((s4.y >> shift) >> 8) == hi) atomicAdd(&hw[(s4.y >> shift) & 255], 1);
                if (((s4.z >> shift) >> 8) == hi) atomicAdd(&hw[(s4.z >> shift) & 255], 1);
                if (((s4.w >> shift) >> 8) == hi) atomicAdd(&hw[(s4.w >> shift) & 255], 1);
            }
        }
        __syncwarp();
        int gs = 0;
#pragma unroll
        for (int i = 0; i < 8; i++) gs += hw[255 - (lane * 8 + i)];
        int S = gs;
#pragma unroll
        for (int off = 1; off < 32; off <<= 1) {
            int t2 = __shfl_up_sync(0xffffffffu, S, off);
            if (lane >= off) S += t2;
        }
        unsigned bal = __ballot_sync(0xffffffffu, S >= krem);
        int L = __ffs(bal) - 1;
        int SL  = __shfl_sync(0xffffffffu, S, L);
        int gsL = __shfl_sync(0xffffffffu, gs, L);
        int c = SL - gsL, selbin = 255 - L * 8, knew = krem;
#pragma unroll
        for (int i = 0; i < 8; i++) {
            int bn = 255 - (L * 8 + i);
            int hv = hw[bn];
            c += hv;
            if (c >= krem) { selbin = bn; knew = krem - (c - hv); break; }
        }
        prefix |= ((unsigned)selbin) << shift;
        krem = knew;
    }
#pragma unroll
    for (int o = 16; o > 0; o >>= 1)
        umax = max(umax, __shfl_xor_sync(0xffffffffu, umax, o));
    float lmax = u2f(umax);
    unsigned thr = prefix;

    /* -------- softmax: dense weights written back over score row ---- */
    float zs = 0.f;
#pragma unroll
    for (int kt = 0; kt < 8; kt++) {
        uint4 s4 = row4[kt * 32 + lane];
        float w0 = (s4.x >= thr) ? __expf(u2f(s4.x) - lmax) : 0.f;
        float w1 = (s4.y >= thr) ? __expf(u2f(s4.y) - lmax) : 0.f;
        float w2 = (s4.z >= thr) ? __expf(u2f(s4.z) - lmax) : 0.f;
        float w3 = (s4.w >= thr) ? __expf(u2f(s4.w) - lmax) : 0.f;
        ((float4*)row)[kt * 32 + lane] = make_float4(w0, w1, w2, w3);
        zs += w0 + w1 + w2 + w3;
    }
#pragma unroll
    for (int o = 16; o > 0; o >>= 1) zs += __shfl_xor_sync(0xffffffffu, zs, o);
    if (lane == 0) rzs[w] = 1.f / zs;
    __syncthreads();   /* all weights + rz visible to all warps */

    /* -------- phase 3: O = W @ V via 3xTF32 mma (dense) ------------- */
    float av[4][4];
#pragma unroll
    for (int nt = 0; nt < 4; nt++)
#pragma unroll
        for (int i = 0; i < 4; i++) av[nt][i] = 0.f;
    {
        const float* scwf = (const float*)scu;
        const unsigned* VH = g_Vhi + ((size_t)bh * LL + w * 64) * 32;
        const unsigned* VL = g_Vlo + ((size_t)bh * LL + w * 64) * 32;
#pragma unroll
        for (int s = 0; s < 8; s++) {
            int k = w * 64 + s * 8;
            float w00 = scwf[g * SC_PITCH + k + tg];
            float w10 = scwf[(g + 8) * SC_PITCH + k + tg];
            float w01 = scwf[g * SC_PITCH + k + tg + 4];
            float w11 = scwf[(g + 8) * SC_PITCH + k + tg + 4];
            unsigned a0h, a0l, a1h, a1l, a2h, a2l, a3h, a3l;
            split_tf32(w00, a0h, a0l);
            split_tf32(w10, a1h, a1l);
            split_tf32(w01, a2h, a2l);
            split_tf32(w11, a3h, a3l);
            int r0 = (s * 8 + tg) * 32;
            int r1 = (s * 8 + tg + 4) * 32;
#pragma unroll
            for (int nt = 0; nt < 4; nt++) {
                int c = nt * 8 + g;
                unsigned b0h = VH[r0 + c], b1h = VH[r1 + c];
                unsigned b0l = VL[r0 + c], b1l = VL[r1 + c];
                float* d = av[nt];
                mma_tf32(d[0], d[1], d[2], d[3], a0h, a1h, a2h, a3h, b0h, b1h);
                mma_tf32(d[0], d[1], d[2], d[3], a0l, a1l, a2l, a3l, b0h, b1h);
                mma_tf32(d[0], d[1], d[2], d[3], a0h, a1h, a2h, a3h, b0l, b1l);
            }
        }
    }

    /* -------- cross-warp reduction of AV partials (2 d-halves) ------ */
    float* P = smx + HIST_OFF;   /* 4096 floats; hist is dead */
#pragma unroll
    for (int hh = 0; hh < 2; hh++) {
        __syncthreads();
#pragma unroll
        for (int nt = hh * 2; nt < hh * 2 + 2; nt++) {
            int dl = (nt - hh * 2) * 8 + tg * 2;
            P[w * 256 + g * 16 + dl]           = av[nt][0];
            P[w * 256 + g * 16 + dl + 1]       = av[nt][1];
            P[w * 256 + (g + 8) * 16 + dl]     = av[nt][2];
            P[w * 256 + (g + 8) * 16 + dl + 1] = av[nt][3];
        }
        __syncthreads();
        if (tid < 256) {
            int q = tid >> 4, dl = tid & 15;
            float s = 0.f;
#pragma unroll
            for (int w2 = 0; w2 < 16; w2++) s += P[w2 * 256 + q * 16 + dl];
            O[(tokbase + qbase + q) * 256 + h * 32 + hh * 16 + dl] = s * rzs[q];
        }
    }
}

/* ------------------------------------------------------------------ */
/* Volatilite: vol[b,j] = std over L of F[b,:,j]                       */
/* ------------------------------------------------------------------ */
__global__ void vol_kernel(const float* __restrict__ F) {
    int tx = threadIdx.x & 127;
    int ty = threadIdx.x >> 7;
    int j = blockIdx.x * 128 + tx;
    int b = blockIdx.y;
    float s = 0.f, ss = 0.f;
    for (int l = ty; l < LL; l += 4) {
        float v = F[((size_t)(b * LL + l)) * DFF + j];
        s += v; ss += v * v;
    }
    __shared__ float sh1[4][128], sh2[4][128];
    sh1[ty][tx] = s; sh2[ty][tx] = ss;
    __syncthreads();
    if (ty == 0) {
        s  = sh1[0][tx] + sh1[1][tx] + sh1[2][tx] + sh1[3][tx];
        ss = sh2[0][tx] + sh2[1][tx] + sh2[2][tx] + sh2[3][tx];
        float mean = s * (1.f / LL);
        float var  = ss * (1.f / LL) - mean * mean;
        g_VOL[b * DFF + j] = sqrtf(fmaxf(var, 0.f));
    }
}

/* ------------------------------------------------------------------ */
extern "C" void kernel_launch(void* const* d_in, const int* in_sizes, int n_in,
                              void* d_out, int out_size) {
    const float* x     = (const float*)d_in[0];
    const float* in_w  = (const float*)d_in[1];
    const float* in_b  = (const float*)d_in[2];
    const float* ln1_g = (const float*)d_in[3];
    const float* ln1_b = (const float*)d_in[4];
    const float* qkv_w = (const float*)d_in[5];
    const float* qkv_b = (const float*)d_in[6];
    const float* out_w = (const float*)d_in[7];
    const float* out_b = (const float*)d_in[8];
    const float* lna_g = (const float*)d_in[9];
    const float* lna_b = (const float*)d_in[10];
    const float* ln2_g = (const float*)d_in[11];
    const float* ln2_b = (const float*)d_in[12];
    const float* ff1_w = (const float*)d_in[13];
    const float* ff1_b = (const float*)d_in[14];
    const float* ff2_w = (const float*)d_in[15];
    const float* ff2_b = (const float*)d_in[16];
    const float* lnf_g = (const float*)d_in[17];
    const float* lnf_b = (const float*)d_in[18];
    float* out = (float*)d_out;

    float *H, *S, *Q, *O, *P, *F;
    cudaGetSymbolAddress((void**)&H, g_H);
    cudaGetSymbolAddress((void**)&S, g_S);
    cudaGetSymbolAddress((void**)&Q, g_QKV);
    cudaGetSymbolAddress((void**)&O, g_O);
    cudaGetSymbolAddress((void**)&P, g_P);
    cudaGetSymbolAddress((void**)&F, g_F);

    cudaFuncSetAttribute((const void*)attn_kernel,
                         cudaFuncAttributeMaxDynamicSharedMemorySize, ATTN_SMEM);

    embed_kernel<<<TT, 256>>>(x, in_w, in_b);

    for (int layer = 0; layer < NLAY; layer++) {
        /* s2 = LN1(h) */
        ln_kernel<<<TT / 8, 256>>>(H, ln1_g, ln1_b, S);
        /* qkv = s2 @ qkv_w + qkv_b */
        gemm_kernel<false, false><<<dim3(768 / 64, TT / 128), 256>>>(
            S, qkv_w, qkv_b, Q, TT, 768, DM);
        /* K -> tf32 hi/lo transposed, V -> tf32 hi/lo native */
        kvconv_kernel<<<dim3(32, BB * NH), 256>>>();
        /* probsparse attention */
        attn_kernel<<<dim3(LL / 16, BB * NH), 512, ATTN_SMEM>>>(Q, O);
        /* P = O @ out_w + out_b */
        gemm_kernel<false, false><<<dim3(256 / 64, TT / 128), 256>>>(
            O, out_w, out_b, P, TT, DM, DM);
        /* h += LN(P + s2);  s2 = LN2(h)   (fused) */
        lna_ln2_kernel<<<TT / 8, 256>>>(P, S, lna_g, lna_b, ln2_g, ln2_b, H);
        /* F = s2 @ ff1_w + ff1_b */
        gemm_kernel<false, false><<<dim3(1024 / 64, TT / 128), 256>>>(
            S, ff1_w, ff1_b, F, TT, DFF, DM);
        /* vol[b,j] */
        vol_kernel<<<dim3(DFF / 128, BB), 512>>>(F);
        /* h += (F * vol) @ ff2_w + ff2_b */
        gemm_kernel<true, true><<<dim3(256 / 64, TT / 128), 256>>>(
            F, ff2_w, ff2_b, H, TT, DM, DFF);
    }

    /* out = LN_f(h) */
    ln_kernel<<<TT / 8, 256>>>(H, lnf_g, lnf_b, out);
}

// round 16
// speedup vs baseline: 1.1362x; 1.0852x over previous
#include <cuda_runtime.h>
#include <math.h>
#include <stdint.h>

#define DM   256
#define NH   8
#define DK   32
#define DFF  1024
#define NLAY 6
#define BB   8
#define LL   1024
#define TT   (BB * LL)     /* 8192 tokens */
#define TOPK 256
#define EPSF 1e-5f

/* ------------------------------------------------------------------ */
/* scratch (static device globals: no runtime allocation)             */
/* ------------------------------------------------------------------ */
__device__ float g_H[TT * DM];
__device__ float g_S[TT * DM];
__device__ float g_QKV[TT * 3 * DM];
__device__ float g_O[TT * DM];
__device__ float g_P[TT * DM];
__device__ float g_F[TT * DFF];
__device__ float g_VOL[BB * DFF];
/* transposed tf32 split of K (scale folded in): [bh][32 dims][1024 keys] */
__device__ unsigned g_KThi[BB * NH * DK * LL];
__device__ unsigned g_KTlo[BB * NH * DK * LL];
/* tf32 of V (hi only), native layout: [bh][1024 keys][32 dims] */
__device__ unsigned g_Vhi[BB * NH * LL * DK];

/* ------------------------------------------------------------------ */
/* tf32 helpers (mapping validated by passing 3xTF32 GEMM)             */
/* ------------------------------------------------------------------ */
__device__ __forceinline__ unsigned cvt_tf32(float x) {
    unsigned r;
    asm("cvt.rna.tf32.f32 %0, %1;" : "=r"(r) : "f"(x));
    return r;
}
__device__ __forceinline__ void split_tf32(float x, unsigned& hi, unsigned& lo) {
    hi = cvt_tf32(x);
    lo = cvt_tf32(x - __uint_as_float(hi));
}
__device__ __forceinline__ void mma_tf32(float& d0, float& d1, float& d2, float& d3,
                                         unsigned a0, unsigned a1, unsigned a2, unsigned a3,
                                         unsigned b0, unsigned b1) {
    asm volatile(
        "mma.sync.aligned.m16n8k8.row.col.f32.tf32.tf32.f32 "
        "{%0,%1,%2,%3},{%4,%5,%6,%7},{%8,%9},{%0,%1,%2,%3};"
        : "+f"(d0), "+f"(d1), "+f"(d2), "+f"(d3)
        : "r"(a0), "r"(a1), "r"(a2), "r"(a3), "r"(b0), "r"(b1));
}

/* ------------------------------------------------------------------ */
/* embed: h = x @ in_w + in_b + PE                                     */
/* ------------------------------------------------------------------ */
__global__ void embed_kernel(const float* __restrict__ x,
                             const float* __restrict__ in_w,
                             const float* __restrict__ in_b) {
    int t = blockIdx.x;
    int d = threadIdx.x;
    int l = t & (LL - 1);
    const float c = -9.210340371976184f / 256.0f;  /* -ln(10000)/256 */
    float div = expf((float)(d & ~1) * c);
    float ang = (float)l * div;
    float pe = (d & 1) ? cosf(ang) : sinf(ang);
    g_H[(size_t)t * DM + d] =
        x[t * 2 + 0] * in_w[d] + x[t * 2 + 1] * in_w[DM + d] + in_b[d] + pe;
}

/* ------------------------------------------------------------------ */
/* LayerNorm: warp per token, 8 tokens per 256-thread block            */
/* ------------------------------------------------------------------ */
__device__ __forceinline__ void warp_reduce_2(float& s, float& q) {
#pragma unroll
    for (int o = 16; o > 0; o >>= 1) {
        s += __shfl_xor_sync(0xffffffffu, s, o);
        q += __shfl_xor_sync(0xffffffffu, q, o);
    }
}

__device__ __forceinline__ float4 ln_apply(float4 v, float mean, float r,
                                           float4 g, float4 b) {
    float4 o;
    o.x = (v.x - mean) * r * g.x + b.x;
    o.y = (v.y - mean) * r * g.y + b.y;
    o.z = (v.z - mean) * r * g.z + b.z;
    o.w = (v.w - mean) * r * g.w + b.w;
    return o;
}

/* dst = LN(src) */
__global__ void ln_kernel(const float* __restrict__ src,
                          const float* __restrict__ g,
                          const float* __restrict__ bt,
                          float* __restrict__ dst) {
    int w = threadIdx.x >> 5, lane = threadIdx.x & 31;
    size_t t = (size_t)blockIdx.x * 8 + w;
    const float4* s4 = (const float4*)(src + t * DM);
    float4 a = s4[lane * 2], b = s4[lane * 2 + 1];
    float s = a.x + a.y + a.z + a.w + b.x + b.y + b.z + b.w;
    float q = a.x*a.x + a.y*a.y + a.z*a.z + a.w*a.w
            + b.x*b.x + b.y*b.y + b.z*b.z + b.w*b.w;
    warp_reduce_2(s, q);
    float mean = s * (1.f / DM);
    float var  = q * (1.f / DM) - mean * mean;
    float r = rsqrtf(var + EPSF);
    float4 g0 = ((const float4*)g)[lane * 2], g1 = ((const float4*)g)[lane * 2 + 1];
    float4 b0 = ((const float4*)bt)[lane * 2], b1 = ((const float4*)bt)[lane * 2 + 1];
    float4* d4 = (float4*)(dst + t * DM);
    d4[lane * 2]     = ln_apply(a, mean, r, g0, b0);
    d4[lane * 2 + 1] = ln_apply(b, mean, r, g1, b1);
}

/* fused: H += LN_a(P + S);  S = LN2(H)                                */
__global__ void lna_ln2_kernel(const float* __restrict__ Pp,
                               float* __restrict__ Sp,
                               const float* __restrict__ ga,
                               const float* __restrict__ ba,
                               const float* __restrict__ g2,
                               const float* __restrict__ b2,
                               float* __restrict__ H) {
    int w = threadIdx.x >> 5, lane = threadIdx.x & 31;
    size_t t = (size_t)blockIdx.x * 8 + w;
    const float4* p4 = (const float4*)(Pp + t * DM);
    const float4* s4 = (const float4*)(Sp + t * DM);
    float4 pa = p4[lane * 2], pb = p4[lane * 2 + 1];
    float4 sa = s4[lane * 2], sb = s4[lane * 2 + 1];
    float4 a, b;
    a.x = pa.x + sa.x; a.y = pa.y + sa.y; a.z = pa.z + sa.z; a.w = pa.w + sa.w;
    b.x = pb.x + sb.x; b.y = pb.y + sb.y; b.z = pb.z + sb.z; b.w = pb.w + sb.w;
    float s = a.x + a.y + a.z + a.w + b.x + b.y + b.z + b.w;
    float q = a.x*a.x + a.y*a.y + a.z*a.z + a.w*a.w
            + b.x*b.x + b.y*b.y + b.z*b.z + b.w*b.w;
    warp_reduce_2(s, q);
    float mean = s * (1.f / DM);
    float var  = q * (1.f / DM) - mean * mean;
    float r = rsqrtf(var + EPSF);
    float4 g0 = ((const float4*)ga)[lane * 2], g1 = ((const float4*)ga)[lane * 2 + 1];
    float4 c0 = ((const float4*)ba)[lane * 2], c1 = ((const float4*)ba)[lane * 2 + 1];
    float4 r0 = ln_apply(a, mean, r, g0, c0);
    float4 r1 = ln_apply(b, mean, r, g1, c1);
    /* h' = H + LN_a(P+S) */
    float4* h4 = (float4*)(H + t * DM);
    float4 h0 = h4[lane * 2], h1 = h4[lane * 2 + 1];
    h0.x += r0.x; h0.y += r0.y; h0.z += r0.z; h0.w += r0.w;
    h1.x += r1.x; h1.y += r1.y; h1.z += r1.z; h1.w += r1.w;
    h4[lane * 2]     = h0;
    h4[lane * 2 + 1] = h1;
    /* S = LN2(h') computed from registers */
    float s2 = h0.x + h0.y + h0.z + h0.w + h1.x + h1.y + h1.z + h1.w;
    float q2 = h0.x*h0.x + h0.y*h0.y + h0.z*h0.z + h0.w*h0.w
             + h1.x*h1.x + h1.y*h1.y + h1.z*h1.z + h1.w*h1.w;
    warp_reduce_2(s2, q2);
    float mean2 = s2 * (1.f / DM);
    float var2  = q2 * (1.f / DM) - mean2 * mean2;
    float r2 = rsqrtf(var2 + EPSF);
    float4 g20 = ((const float4*)g2)[lane * 2], g21 = ((const float4*)g2)[lane * 2 + 1];
    float4 b20 = ((const float4*)b2)[lane * 2], b21 = ((const float4*)b2)[lane * 2 + 1];
    float4* d4 = (float4*)(Sp + t * DM);
    d4[lane * 2]     = ln_apply(h0, mean2, r2, g20, b20);
    d4[lane * 2 + 1] = ln_apply(h1, mean2, r2, g21, b21);
}

/* ------------------------------------------------------------------ */
/* K/V preconvert: K -> tf32 hi/lo transposed (scale folded),          */
/*                 V -> tf32 hi only, native layout                    */
/* ------------------------------------------------------------------ */
__global__ void kvconv_kernel() {
    __shared__ float tile[32][33];
    int bh = blockIdx.y;
    int kt = blockIdx.x;              /* 32 keys per tile */
    int b = bh >> 3, h = bh & 7;
    int t = threadIdx.x;
    size_t tok0 = (size_t)b * LL + kt * 32;
    {
        int kl = t >> 5, d = t & 31;
#pragma unroll
        for (int r = 0; r < 4; r++) {
            int key = kl + r * 8;
            tile[key][d] = g_QKV[(tok0 + key) * 768 + 256 + h * 32 + d];
        }
    }
    {
#pragma unroll
        for (int r = 0; r < 4; r++) {
            int idx = t + r * 256;
            int key = idx >> 5, d = idx & 31;
            float v = g_QKV[(tok0 + key) * 768 + 512 + h * 32 + d];
            size_t o = ((size_t)bh * LL + kt * 32 + key) * 32 + d;
            g_Vhi[o] = cvt_tf32(v);
        }
    }
    __syncthreads();
    {
        int dl = t >> 5, key = t & 31;
        const float scale = 0.17677669529663687f; /* 1/sqrt(32) */
#pragma unroll
        for (int r = 0; r < 4; r++) {
            int d2 = dl + r * 8;
            float v = tile[key][d2] * scale;
            unsigned hi, lo;
            split_tf32(v, hi, lo);
            size_t idx = ((size_t)bh * 32 + d2) * LL + kt * 32 + key;
            g_KThi[idx] = hi;
            g_KTlo[idx] = lo;
        }
    }
}

/* ------------------------------------------------------------------ */
/* 3xTF32 tensor-core GEMM: C[M,N] (=|+=) A[M,K] @ B[K,N] + bias       */
/* BM=128, BN=64, BK=16, 256 threads, warp tile 32x32 (m16n8k8 mma)    */
/* (exact R11 version)                                                 */
/* ------------------------------------------------------------------ */
template <bool ADD, bool USEVOL>
__global__ void __launch_bounds__(256, 2)
gemm_kernel(const float* __restrict__ A,
            const float* __restrict__ Bw,
            const float* __restrict__ bias,
            float* __restrict__ C,
            int M, int N, int K) {
    __shared__ unsigned Abig[16][136], Asml[16][136];
    __shared__ unsigned Bbig[16][72],  Bsml[16][72];

    int tid = threadIdx.x;
    int lane = tid & 31, wid = tid >> 5;
    int g = lane >> 2, tg = lane & 3;
    int wm = (wid >> 1) * 32;
    int wn = (wid & 1) * 32;
    int bn0 = blockIdx.x * 64;
    int bm0 = blockIdx.y * 128;

    const float* volp = USEVOL ? (g_VOL + (size_t)((bm0 >> 10) << 10)) : (const float*)0;

    float acc[2][4][4];
#pragma unroll
    for (int mt = 0; mt < 2; mt++)
#pragma unroll
        for (int nt = 0; nt < 4; nt++)
#pragma unroll
            for (int i = 0; i < 4; i++) acc[mt][nt][i] = 0.f;

    int ar = tid >> 1, ac = (tid & 1) * 8;
    int br = tid >> 4, bc = (tid & 15) * 4;

    for (int k0 = 0; k0 < K; k0 += 16) {
        __syncthreads();
        {
            const float* ap = &A[(size_t)(bm0 + ar) * K + k0 + ac];
            float4 av0 = *(const float4*)ap;
            float4 av1 = *(const float4*)(ap + 4);
            if (USEVOL) {
                av0.x *= volp[k0 + ac + 0]; av0.y *= volp[k0 + ac + 1];
                av0.z *= volp[k0 + ac + 2]; av0.w *= volp[k0 + ac + 3];
                av1.x *= volp[k0 + ac + 4]; av1.y *= volp[k0 + ac + 5];
                av1.z *= volp[k0 + ac + 6]; av1.w *= volp[k0 + ac + 7];
            }
            float xs[8] = {av0.x, av0.y, av0.z, av0.w,
                           av1.x, av1.y, av1.z, av1.w};
#pragma unroll
            for (int j = 0; j < 8; j++) {
                unsigned hi, lo;
                split_tf32(xs[j], hi, lo);
                Abig[ac + j][ar] = hi;
                Asml[ac + j][ar] = lo;
            }
            const float* bp = &Bw[(size_t)(k0 + br) * N + bn0 + bc];
            float4 bv = *(const float4*)bp;
            uint4 hb, lb;
            split_tf32(bv.x, hb.x, lb.x);
            split_tf32(bv.y, hb.y, lb.y);
            split_tf32(bv.z, hb.z, lb.z);
            split_tf32(bv.w, hb.w, lb.w);
            *(uint4*)&Bbig[br][bc] = hb;
            *(uint4*)&Bsml[br][bc] = lb;
        }
        __syncthreads();

#pragma unroll
        for (int ks = 0; ks < 2; ks++) {
            int kb = ks * 8;
            unsigned ab[2][4], al[2][4];
#pragma unroll
            for (int mt = 0; mt < 2; mt++) {
                int m0 = wm + mt * 16 + g;
                ab[mt][0] = Abig[kb + tg    ][m0];
                ab[mt][1] = Abig[kb + tg    ][m0 + 8];
                ab[mt][2] = Abig[kb + tg + 4][m0];
                ab[mt][3] = Abig[kb + tg + 4][m0 + 8];
                al[mt][0] = Asml[kb + tg    ][m0];
                al[mt][1] = Asml[kb + tg    ][m0 + 8];
                al[mt][2] = Asml[kb + tg + 4][m0];
                al[mt][3] = Asml[kb + tg + 4][m0 + 8];
            }
            unsigned bb[4][2], bl[4][2];
#pragma unroll
            for (int nt = 0; nt < 4; nt++) {
                int n0 = wn + nt * 8 + g;
                bb[nt][0] = Bbig[kb + tg    ][n0];
                bb[nt][1] = Bbig[kb + tg + 4][n0];
                bl[nt][0] = Bsml[kb + tg    ][n0];
                bl[nt][1] = Bsml[kb + tg + 4][n0];
            }
#pragma unroll
            for (int mt = 0; mt < 2; mt++)
#pragma unroll
                for (int nt = 0; nt < 4; nt++) {
                    float* d = acc[mt][nt];
                    mma_tf32(d[0], d[1], d[2], d[3],
                             ab[mt][0], ab[mt][1], ab[mt][2], ab[mt][3],
                             bb[nt][0], bb[nt][1]);
                    mma_tf32(d[0], d[1], d[2], d[3],
                             al[mt][0], al[mt][1], al[mt][2], al[mt][3],
                             bb[nt][0], bb[nt][1]);
                    mma_tf32(d[0], d[1], d[2], d[3],
                             ab[mt][0], ab[mt][1], ab[mt][2], ab[mt][3],
                             bl[nt][0], bl[nt][1]);
                }
        }
    }

#pragma unroll
    for (int mt = 0; mt < 2; mt++)
#pragma unroll
        for (int nt = 0; nt < 4; nt++) {
            int r0 = bm0 + wm + mt * 16 + g;
            int c0 = bn0 + wn + nt * 8 + tg * 2;
            float2 bi = *(const float2*)&bias[c0];
            float* p0 = &C[(size_t)r0 * N + c0];
            float* p1 = &C[(size_t)(r0 + 8) * N + c0];
            float2 v0, v1;
            v0.x = acc[mt][nt][0] + bi.x; v0.y = acc[mt][nt][1] + bi.y;
            v1.x = acc[mt][nt][2] + bi.x; v1.y = acc[mt][nt][3] + bi.y;
            if (ADD) {
                float2 o0 = *(float2*)p0, o1 = *(float2*)p1;
                v0.x += o0.x; v0.y += o0.y;
                v1.x += o1.x; v1.y += o1.y;
            }
            *(float2*)p0 = v0;
            *(float2*)p1 = v1;
        }
}

/* ------------------------------------------------------------------ */
/* ProbSparse attention, 16 queries per 512-thread block               */
/* phase 1 (QK^T) 3xTF32, phase 3 (AV) 2xTF32 (V hi-only)              */
/* ------------------------------------------------------------------ */
#define SC_PITCH  1032
#define SC_OFF    0
#define HIST_OFF  16512
#define QHI_OFF   20608
#define QLO_OFF   21184
#define RZ_OFF    21760
#define ATTN_SMEM (21776 * 4)

__device__ __forceinline__ unsigned f2u(float f) {
    unsigned u = __float_as_uint(f);
    return (u & 0x80000000u) ? ~u : (u | 0x80000000u);
}
__device__ __forceinline__ float u2f(unsigned x) {
    unsigned v = (x & 0x80000000u) ? (x ^ 0x80000000u) : ~x;
    return __uint_as_float(v);
}

__global__ void __launch_bounds__(512, 2)
attn_kernel(const float* __restrict__ QKV, float* __restrict__ O) {
    extern __shared__ float smx[];
    unsigned* scu  = (unsigned*)(smx + SC_OFF);   /* u32 scores -> fp32 weights */
    int*      histb = (int*)(smx + HIST_OFF);     /* later: AV partials */
    unsigned* Qhi  = (unsigned*)(smx + QHI_OFF);
    unsigned* Qlo  = (unsigned*)(smx + QLO_OFF);
    float*    rzs  = smx + RZ_OFF;

    int tid = threadIdx.x, lane = tid & 31, w = tid >> 5;
    int bh = blockIdx.y, b = bh >> 3, h = bh & 7;
    int qbase = blockIdx.x * 16;
    size_t tokbase = (size_t)b * LL;
    const float* base = QKV + tokbase * 768 + h * 32;

    /* stage Q tile as tf32 hi/lo: 16 x 32, pitch 36 */
    {
        int q = tid >> 5, d = tid & 31;
        float qv = base[(size_t)(qbase + q) * 768 + d];
        unsigned hi, lo;
        split_tf32(qv, hi, lo);
        Qhi[q * 36 + d] = hi;
        Qlo[q * 36 + d] = lo;
    }
    __syncthreads();

    int g = lane >> 2, tg = lane & 3;

    /* ---------------- phase 1: S = Q K^T via 3xTF32 mma ------------- */
    {
        unsigned ah[4][4], al[4][4];
#pragma unroll
        for (int s = 0; s < 4; s++) {
            int d0 = s * 8;
            ah[s][0] = Qhi[g * 36 + d0 + tg];
            ah[s][1] = Qhi[(g + 8) * 36 + d0 + tg];
            ah[s][2] = Qhi[g * 36 + d0 + tg + 4];
            ah[s][3] = Qhi[(g + 8) * 36 + d0 + tg + 4];
            al[s][0] = Qlo[g * 36 + d0 + tg];
            al[s][1] = Qlo[(g + 8) * 36 + d0 + tg];
            al[s][2] = Qlo[g * 36 + d0 + tg + 4];
            al[s][3] = Qlo[(g + 8) * 36 + d0 + tg + 4];
        }
        const unsigned* KH = g_KThi + (size_t)bh * 32 * LL;
        const unsigned* KL = g_KTlo + (size_t)bh * 32 * LL;
        int off0 = tg * LL + g;
        int off1 = (tg + 4) * LL + g;
#pragma unroll
        for (int kg = 0; kg < 8; kg++) {
            int kb = w * 64 + kg * 8;
            float c0 = 0.f, c1 = 0.f, c2 = 0.f, c3 = 0.f;
#pragma unroll
            for (int s = 0; s < 4; s++) {
                unsigned b0h = KH[s * 8 * LL + kb + off0];
                unsigned b1h = KH[s * 8 * LL + kb + off1];
                unsigned b0l = KL[s * 8 * LL + kb + off0];
                unsigned b1l = KL[s * 8 * LL + kb + off1];
                mma_tf32(c0, c1, c2, c3,
                         ah[s][0], ah[s][1], ah[s][2], ah[s][3], b0h, b1h);
                mma_tf32(c0, c1, c2, c3,
                         al[s][0], al[s][1], al[s][2], al[s][3], b0h, b1h);
                mma_tf32(c0, c1, c2, c3,
                         ah[s][0], ah[s][1], ah[s][2], ah[s][3], b0l, b1l);
            }
            int cc = kb + tg * 2;
            uint2 p0 = make_uint2(f2u(c0), f2u(c1));
            uint2 p1 = make_uint2(f2u(c2), f2u(c3));
            *(uint2*)&scu[g * SC_PITCH + cc]       = p0;
            *(uint2*)&scu[(g + 8) * SC_PITCH + cc] = p1;
        }
    }
    __syncthreads();

    unsigned* row = scu + w * SC_PITCH;
    const uint4* row4 = (const uint4*)row;

    /* -------- phase 2: exact 256-th largest (4-pass radix, u32) ----- */
    int* hw = histb + w * 256;
    unsigned prefix = 0, umax = 0;
    int krem = TOPK;
#pragma unroll
    for (int pass = 0; pass < 4; pass++) {
        int shift = 24 - 8 * pass;
        for (int i = lane; i < 256; i += 32) hw[i] = 0;
        __syncwarp();
        for (int j4 = lane; j4 < 256; j4 += 32) {
            uint4 s4 = row4[j4];
            if (pass == 0) {
                umax = max(max(umax, s4.x), max(s4.y, max(s4.z, s4.w)));
                atomicAdd(&hw[s4.x >> 24], 1);
                atomicAdd(&hw[s4.y >> 24], 1);
                atomicAdd(&hw[s4.z >> 24], 1);
                atomicAdd(&hw[s4.w >> 24], 1);
            } else {
                unsigned hi = (prefix >> shift) >> 8;
                if (((s4.x >> shift) >> 8) == hi) atomicAdd(&hw[(s4.x >> shift) & 255], 1);
                if (((s4.y >> shift) >> 8) == hi) atomicAdd(&hw[(s4.y >> shift) & 255], 1);
                if (((s4.z >> shift) >> 8) == hi) atomicAdd(&hw[(s4.z >> shift) & 255], 1);
                if (((s4.w >> shift) >> 8) == hi) atomicAdd(&hw[(s4.w >> shift) & 255], 1);
            }
        }
        __syncwarp();
        int gs = 0;
#pragma unroll
        for (int i = 0; i < 8; i++) gs += hw[255 - (lane * 8 + i)];
        int S = gs;
#pragma unroll
        for (int off = 1; off < 32; off <<= 1) {
            int t2 = __shfl_up_sync(0xffffffffu, S, off);
            if (lane >= off) S += t2;
        }
        unsigned bal = __ballot_sync(0xffffffffu, S >= krem);
        int L = __ffs(bal) - 1;
        int SL  = __shfl_sync(0xffffffffu, S, L);
        int gsL = __shfl_sync(0xffffffffu, gs, L);
        int c = SL - gsL, selbin = 255 - L * 8, knew = krem;
#pragma unroll
        for (int i = 0; i < 8; i++) {
            int bn = 255 - (L * 8 + i);
            int hv = hw[bn];
            c += hv;
            if (c >= krem) { selbin = bn; knew = krem - (c - hv); break; }
        }
        prefix |= ((unsigned)selbin) << shift;
        krem = knew;
    }
#pragma unroll
    for (int o = 16; o > 0; o >>= 1)
        umax = max(umax, __shfl_xor_sync(0xffffffffu, umax, o));
    float lmax = u2f(umax);
    unsigned thr = prefix;

    /* -------- softmax: dense weights written back over score row ---- */
    float zs = 0.f;
#pragma unroll
    for (int kt = 0; kt < 8; kt++) {
        uint4 s4 = row4[kt * 32 + lane];
        float w0 = (s4.x >= thr) ? __expf(u2f(s4.x) - lmax) : 0.f;
        float w1 = (s4.y >= thr) ? __expf(u2f(s4.y) - lmax) : 0.f;
        float w2 = (s4.z >= thr) ? __expf(u2f(s4.z) - lmax) : 0.f;
        float w3 = (s4.w >= thr) ? __expf(u2f(s4.w) - lmax) : 0.f;
        ((float4*)row)[kt * 32 + lane] = make_float4(w0, w1, w2, w3);
        zs += w0 + w1 + w2 + w3;
    }
#pragma unroll
    for (int o = 16; o > 0; o >>= 1) zs += __shfl_xor_sync(0xffffffffu, zs, o);
    if (lane == 0) rzs[w] = 1.f / zs;
    __syncthreads();   /* all weights + rz visible to all warps */

    /* -------- phase 3: O = W @ V via 2xTF32 mma (V hi-only) --------- */
    float av[4][4];
#pragma unroll
    for (int nt = 0; nt < 4; nt++)
#pragma unroll
        for (int i = 0; i < 4; i++) av[nt][i] = 0.f;
    {
        const float* scwf = (const float*)scu;
        const unsigned* VH = g_Vhi + ((size_t)bh * LL + w * 64) * 32;
#pragma unroll
        for (int s = 0; s < 8; s++) {
            int k = w * 64 + s * 8;
            float w00 = scwf[g * SC_PITCH + k + tg];
            float w10 = scwf[(g + 8) * SC_PITCH + k + tg];
            float w01 = scwf[g * SC_PITCH + k + tg + 4];
            float w11 = scwf[(g + 8) * SC_PITCH + k + tg + 4];
            unsigned a0h, a0l, a1h, a1l, a2h, a2l, a3h, a3l;
            split_tf32(w00, a0h, a0l);
            split_tf32(w10, a1h, a1l);
            split_tf32(w01, a2h, a2l);
            split_tf32(w11, a3h, a3l);
            int r0 = (s * 8 + tg) * 32;
            int r1 = (s * 8 + tg + 4) * 32;
#pragma unroll
            for (int nt = 0; nt < 4; nt++) {
                int c = nt * 8 + g;
                unsigned b0h = VH[r0 + c], b1h = VH[r1 + c];
                float* d = av[nt];
                mma_tf32(d[0], d[1], d[2], d[3], a0h, a1h, a2h, a3h, b0h, b1h);
                mma_tf32(d[0], d[1], d[2], d[3], a0l, a1l, a2l, a3l, b0h, b1h);
            }
        }
    }

    /* -------- cross-warp reduction of AV partials (2 d-halves) ------ */
    float* P = smx + HIST_OFF;   /* 4096 floats; hist is dead */
#pragma unroll
    for (int hh = 0; hh < 2; hh++) {
        __syncthreads();
#pragma unroll
        for (int nt = hh * 2; nt < hh * 2 + 2; nt++) {
            int dl = (nt - hh * 2) * 8 + tg * 2;
            P[w * 256 + g * 16 + dl]           = av[nt][0];
            P[w * 256 + g * 16 + dl + 1]       = av[nt][1];
            P[w * 256 + (g + 8) * 16 + dl]     = av[nt][2];
            P[w * 256 + (g + 8) * 16 + dl + 1] = av[nt][3];
        }
        __syncthreads();
        if (tid < 256) {
            int q = tid >> 4, dl = tid & 15;
            float s = 0.f;
#pragma unroll
            for (int w2 = 0; w2 < 16; w2++) s += P[w2 * 256 + q * 16 + dl];
            O[(tokbase + qbase + q) * 256 + h * 32 + hh * 16 + dl] = s * rzs[q];
        }
    }
}

/* ------------------------------------------------------------------ */
/* Volatilite: vol[b,j] = std over L of F[b,:,j]                       */
/* ------------------------------------------------------------------ */
__global__ void vol_kernel(const float* __restrict__ F) {
    int tx = threadIdx.x & 127;
    int ty = threadIdx.x >> 7;
    int j = blockIdx.x * 128 + tx;
    int b = blockIdx.y;
    float s = 0.f, ss = 0.f;
    for (int l = ty; l < LL; l += 4) {
        float v = F[((size_t)(b * LL + l)) * DFF + j];
        s += v; ss += v * v;
    }
    __shared__ float sh1[4][128], sh2[4][128];
    sh1[ty][tx] = s; sh2[ty][tx] = ss;
    __syncthreads();
    if (ty == 0) {
        s  = sh1[0][tx] + sh1[1][tx] + sh1[2][tx] + sh1[3][tx];
        ss = sh2[0][tx] + sh2[1][tx] + sh2[2][tx] + sh2[3][tx];
        float mean = s * (1.f / LL);
        float var  = ss * (1.f / LL) - mean * mean;
        g_VOL[b * DFF + j] = sqrtf(fmaxf(var, 0.f));
    }
}

/* ------------------------------------------------------------------ */
extern "C" void kernel_launch(void* const* d_in, const int* in_sizes, int n_in,
                              void* d_out, int out_size) {
    const float* x     = (const float*)d_in[0];
    const float* in_w  = (const float*)d_in[1];
    const float* in_b  = (const float*)d_in[2];
    const float* ln1_g = (const float*)d_in[3];
    const float* ln1_b = (const float*)d_in[4];
    const float* qkv_w = (const float*)d_in[5];
    const float* qkv_b = (const float*)d_in[6];
    const float* out_w = (const float*)d_in[7];
    const float* out_b = (const float*)d_in[8];
    const float* lna_g = (const float*)d_in[9];
    const float* lna_b = (const float*)d_in[10];
    const float* ln2_g = (const float*)d_in[11];
    const float* ln2_b = (const float*)d_in[12];
    const float* ff1_w = (const float*)d_in[13];
    const float* ff1_b = (const float*)d_in[14];
    const float* ff2_w = (const float*)d_in[15];
    const float* ff2_b = (const float*)d_in[16];
    const float* lnf_g = (const float*)d_in[17];
    const float* lnf_b = (const float*)d_in[18];
    float* out = (float*)d_out;

    float *H, *S, *Q, *O, *P, *F;
    cudaGetSymbolAddress((void**)&H, g_H);
    cudaGetSymbolAddress((void**)&S, g_S);
    cudaGetSymbolAddress((void**)&Q, g_QKV);
    cudaGetSymbolAddress((void**)&O, g_O);
    cudaGetSymbolAddress((void**)&P, g_P);
    cudaGetSymbolAddress((void**)&F, g_F);

    cudaFuncSetAttribute((const void*)attn_kernel,
                         cudaFuncAttributeMaxDynamicSharedMemorySize, ATTN_SMEM);

    embed_kernel<<<TT, 256>>>(x, in_w, in_b);

    for (int layer = 0; layer < NLAY; layer++) {
        /* s2 = LN1(h) */
        ln_kernel<<<TT / 8, 256>>>(H, ln1_g, ln1_b, S);
        /* qkv = s2 @ qkv_w + qkv_b */
        gemm_kernel<false, false><<<dim3(768 / 64, TT / 128), 256>>>(
            S, qkv_w, qkv_b, Q, TT, 768, DM);
        /* K -> tf32 hi/lo transposed, V -> tf32 hi native */
        kvconv_kernel<<<dim3(32, BB * NH), 256>>>();
        /* probsparse attention */
        attn_kernel<<<dim3(LL / 16, BB * NH), 512, ATTN_SMEM>>>(Q, O);
        /* P = O @ out_w + out_b */
        gemm_kernel<false, false><<<dim3(256 / 64, TT / 128), 256>>>(
            O, out_w, out_b, P, TT, DM, DM);
        /* h += LN(P + s2);  s2 = LN2(h)   (fused) */
        lna_ln2_kernel<<<TT / 8, 256>>>(P, S, lna_g, lna_b, ln2_g, ln2_b, H);
        /* F = s2 @ ff1_w + ff1_b */
        gemm_kernel<false, false><<<dim3(1024 / 64, TT / 128), 256>>>(
            S, ff1_w, ff1_b, F, TT, DFF, DM);
        /* vol[b,j] */
        vol_kernel<<<dim3(DFF / 128, BB), 512>>>(F);
        /* h += (F * vol) @ ff2_w + ff2_b */
        gemm_kernel<true, true><<<dim3(256 / 64, TT / 128), 256>>>(
            F, ff2_w, ff2_b, H, TT, DM, DFF);
    }

    /* out = LN_f(h) */
    ln_kernel<<<TT / 8, 256>>>(H, lnf_g, lnf_b, out);
}

// round 17
// speedup vs baseline: 1.2047x; 1.0603x over previous
#include <cuda_runtime.h>
#include <math.h>
#include <stdint.h>

#define DM   256
#define NH   8
#define DK   32
#define DFF  1024
#define NLAY 6
#define BB   8
#define LL   1024
#define TT   (BB * LL)     /* 8192 tokens */
#define TOPK 256
#define EPSF 1e-5f

/* ------------------------------------------------------------------ */
/* scratch (static device globals: no runtime allocation)             */
/* ------------------------------------------------------------------ */
__device__ float g_H[TT * DM];
__device__ float g_S[TT * DM];
__device__ float g_QKV[TT * 3 * DM];
__device__ float g_O[TT * DM];
__device__ float g_P[TT * DM];
__device__ float g_F[TT * DFF];
__device__ float g_VOL[BB * DFF];
/* transposed tf32 split of K (scale folded in): [bh][32 dims][1024 keys] */
__device__ unsigned g_KThi[BB * NH * DK * LL];
__device__ unsigned g_KTlo[BB * NH * DK * LL];
/* tf32 of V (hi only), native layout: [bh][1024 keys][32 dims] */
__device__ unsigned g_Vhi[BB * NH * LL * DK];

/* ------------------------------------------------------------------ */
/* tf32 helpers (mapping validated by passing 3xTF32 GEMM)             */
/* ------------------------------------------------------------------ */
__device__ __forceinline__ unsigned cvt_tf32(float x) {
    unsigned r;
    asm("cvt.rna.tf32.f32 %0, %1;" : "=r"(r) : "f"(x));
    return r;
}
__device__ __forceinline__ void split_tf32(float x, unsigned& hi, unsigned& lo) {
    hi = cvt_tf32(x);
    lo = cvt_tf32(x - __uint_as_float(hi));
}
__device__ __forceinline__ void mma_tf32(float& d0, float& d1, float& d2, float& d3,
                                         unsigned a0, unsigned a1, unsigned a2, unsigned a3,
                                         unsigned b0, unsigned b1) {
    asm volatile(
        "mma.sync.aligned.m16n8k8.row.col.f32.tf32.tf32.f32 "
        "{%0,%1,%2,%3},{%4,%5,%6,%7},{%8,%9},{%0,%1,%2,%3};"
        : "+f"(d0), "+f"(d1), "+f"(d2), "+f"(d3)
        : "r"(a0), "r"(a1), "r"(a2), "r"(a3), "r"(b0), "r"(b1));
}

/* ------------------------------------------------------------------ */
/* embed: h = x @ in_w + in_b + PE                                     */
/* ------------------------------------------------------------------ */
__global__ void embed_kernel(const float* __restrict__ x,
                             const float* __restrict__ in_w,
                             const float* __restrict__ in_b) {
    int t = blockIdx.x;
    int d = threadIdx.x;
    int l = t & (LL - 1);
    const float c = -9.210340371976184f / 256.0f;  /* -ln(10000)/256 */
    float div = expf((float)(d & ~1) * c);
    float ang = (float)l * div;
    float pe = (d & 1) ? cosf(ang) : sinf(ang);
    g_H[(size_t)t * DM + d] =
        x[t * 2 + 0] * in_w[d] + x[t * 2 + 1] * in_w[DM + d] + in_b[d] + pe;
}

/* ------------------------------------------------------------------ */
/* LayerNorm: warp per token, 8 tokens per 256-thread block            */
/* ------------------------------------------------------------------ */
__device__ __forceinline__ void warp_reduce_2(float& s, float& q) {
#pragma unroll
    for (int o = 16; o > 0; o >>= 1) {
        s += __shfl_xor_sync(0xffffffffu, s, o);
        q += __shfl_xor_sync(0xffffffffu, q, o);
    }
}

__device__ __forceinline__ float4 ln_apply(float4 v, float mean, float r,
                                           float4 g, float4 b) {
    float4 o;
    o.x = (v.x - mean) * r * g.x + b.x;
    o.y = (v.y - mean) * r * g.y + b.y;
    o.z = (v.z - mean) * r * g.z + b.z;
    o.w = (v.w - mean) * r * g.w + b.w;
    return o;
}

/* dst = LN(src) */
__global__ void ln_kernel(const float* __restrict__ src,
                          const float* __restrict__ g,
                          const float* __restrict__ bt,
                          float* __restrict__ dst) {
    int w = threadIdx.x >> 5, lane = threadIdx.x & 31;
    size_t t = (size_t)blockIdx.x * 8 + w;
    const float4* s4 = (const float4*)(src + t * DM);
    float4 a = s4[lane * 2], b = s4[lane * 2 + 1];
    float s = a.x + a.y + a.z + a.w + b.x + b.y + b.z + b.w;
    float q = a.x*a.x + a.y*a.y + a.z*a.z + a.w*a.w
            + b.x*b.x + b.y*b.y + b.z*b.z + b.w*b.w;
    warp_reduce_2(s, q);
    float mean = s * (1.f / DM);
    float var  = q * (1.f / DM) - mean * mean;
    float r = rsqrtf(var + EPSF);
    float4 g0 = ((const float4*)g)[lane * 2], g1 = ((const float4*)g)[lane * 2 + 1];
    float4 b0 = ((const float4*)bt)[lane * 2], b1 = ((const float4*)bt)[lane * 2 + 1];
    float4* d4 = (float4*)(dst + t * DM);
    d4[lane * 2]     = ln_apply(a, mean, r, g0, b0);
    d4[lane * 2 + 1] = ln_apply(b, mean, r, g1, b1);
}

/* fused: H += LN_a(P + S);  S = LN2(H)                                */
__global__ void lna_ln2_kernel(const float* __restrict__ Pp,
                               float* __restrict__ Sp,
                               const float* __restrict__ ga,
                               const float* __restrict__ ba,
                               const float* __restrict__ g2,
                               const float* __restrict__ b2,
                               float* __restrict__ H) {
    int w = threadIdx.x >> 5, lane = threadIdx.x & 31;
    size_t t = (size_t)blockIdx.x * 8 + w;
    const float4* p4 = (const float4*)(Pp + t * DM);
    const float4* s4 = (const float4*)(Sp + t * DM);
    float4 pa = p4[lane * 2], pb = p4[lane * 2 + 1];
    float4 sa = s4[lane * 2], sb = s4[lane * 2 + 1];
    float4 a, b;
    a.x = pa.x + sa.x; a.y = pa.y + sa.y; a.z = pa.z + sa.z; a.w = pa.w + sa.w;
    b.x = pb.x + sb.x; b.y = pb.y + sb.y; b.z = pb.z + sb.z; b.w = pb.w + sb.w;
    float s = a.x + a.y + a.z + a.w + b.x + b.y + b.z + b.w;
    float q = a.x*a.x + a.y*a.y + a.z*a.z + a.w*a.w
            + b.x*b.x + b.y*b.y + b.z*b.z + b.w*b.w;
    warp_reduce_2(s, q);
    float mean = s * (1.f / DM);
    float var  = q * (1.f / DM) - mean * mean;
    float r = rsqrtf(var + EPSF);
    float4 g0 = ((const float4*)ga)[lane * 2], g1 = ((const float4*)ga)[lane * 2 + 1];
    float4 c0 = ((const float4*)ba)[lane * 2], c1 = ((const float4*)ba)[lane * 2 + 1];
    float4 r0 = ln_apply(a, mean, r, g0, c0);
    float4 r1 = ln_apply(b, mean, r, g1, c1);
    float4* h4 = (float4*)(H + t * DM);
    float4 h0 = h4[lane * 2], h1 = h4[lane * 2 + 1];
    h0.x += r0.x; h0.y += r0.y; h0.z += r0.z; h0.w += r0.w;
    h1.x += r1.x; h1.y += r1.y; h1.z += r1.z; h1.w += r1.w;
    h4[lane * 2]     = h0;
    h4[lane * 2 + 1] = h1;
    float s2 = h0.x + h0.y + h0.z + h0.w + h1.x + h1.y + h1.z + h1.w;
    float q2 = h0.x*h0.x + h0.y*h0.y + h0.z*h0.z + h0.w*h0.w
             + h1.x*h1.x + h1.y*h1.y + h1.z*h1.z + h1.w*h1.w;
    warp_reduce_2(s2, q2);
    float mean2 = s2 * (1.f / DM);
    float var2  = q2 * (1.f / DM) - mean2 * mean2;
    float r2 = rsqrtf(var2 + EPSF);
    float4 g20 = ((const float4*)g2)[lane * 2], g21 = ((const float4*)g2)[lane * 2 + 1];
    float4 b20 = ((const float4*)b2)[lane * 2], b21 = ((const float4*)b2)[lane * 2 + 1];
    float4* d4 = (float4*)(Sp + t * DM);
    d4[lane * 2]     = ln_apply(h0, mean2, r2, g20, b20);
    d4[lane * 2 + 1] = ln_apply(h1, mean2, r2, g21, b21);
}

/* ------------------------------------------------------------------ */
/* K/V preconvert: K -> tf32 hi/lo transposed (scale folded),          */
/*                 V -> tf32 hi only, native layout                    */
/* ------------------------------------------------------------------ */
__global__ void kvconv_kernel() {
    __shared__ float tile[32][33];
    int bh = blockIdx.y;
    int kt = blockIdx.x;              /* 32 keys per tile */
    int b = bh >> 3, h = bh & 7;
    int t = threadIdx.x;
    size_t tok0 = (size_t)b * LL + kt * 32;
    {
        int kl = t >> 5, d = t & 31;
#pragma unroll
        for (int r = 0; r < 4; r++) {
            int key = kl + r * 8;
            tile[key][d] = g_QKV[(tok0 + key) * 768 + 256 + h * 32 + d];
        }
    }
    {
#pragma unroll
        for (int r = 0; r < 4; r++) {
            int idx = t + r * 256;
            int key = idx >> 5, d = idx & 31;
            float v = g_QKV[(tok0 + key) * 768 + 512 + h * 32 + d];
            size_t o = ((size_t)bh * LL + kt * 32 + key) * 32 + d;
            g_Vhi[o] = cvt_tf32(v);
        }
    }
    __syncthreads();
    {
        int dl = t >> 5, key = t & 31;
        const float scale = 0.17677669529663687f; /* 1/sqrt(32) */
#pragma unroll
        for (int r = 0; r < 4; r++) {
            int d2 = dl + r * 8;
            float v = tile[key][d2] * scale;
            unsigned hi, lo;
            split_tf32(v, hi, lo);
            size_t idx = ((size_t)bh * 32 + d2) * LL + kt * 32 + key;
            g_KThi[idx] = hi;
            g_KTlo[idx] = lo;
        }
    }
}

/* ------------------------------------------------------------------ */
/* tensor-core GEMM: C[M,N] (=|+=) A[M,K] @ B[K,N] + bias              */
/* BM=128, BN=64, BK=16, 256 threads, warp tile 32x32 (m16n8k8 mma)    */
/* BLO: include B-lo term (3xTF32); else 2-term (A split x B-hi)       */
/* ------------------------------------------------------------------ */
template <bool ADD, bool USEVOL, bool BLO>
__global__ void __launch_bounds__(256, 2)
gemm_kernel(const float* __restrict__ A,
            const float* __restrict__ Bw,
            const float* __restrict__ bias,
            float* __restrict__ C,
            int M, int N, int K) {
    __shared__ unsigned Abig[16][136], Asml[16][136];
    __shared__ unsigned Bbig[16][72],  Bsml[16][72];

    int tid = threadIdx.x;
    int lane = tid & 31, wid = tid >> 5;
    int g = lane >> 2, tg = lane & 3;
    int wm = (wid >> 1) * 32;
    int wn = (wid & 1) * 32;
    int bn0 = blockIdx.x * 64;
    int bm0 = blockIdx.y * 128;

    const float* volp = USEVOL ? (g_VOL + (size_t)((bm0 >> 10) << 10)) : (const float*)0;

    float acc[2][4][4];
#pragma unroll
    for (int mt = 0; mt < 2; mt++)
#pragma unroll
        for (int nt = 0; nt < 4; nt++)
#pragma unroll
            for (int i = 0; i < 4; i++) acc[mt][nt][i] = 0.f;

    int ar = tid >> 1, ac = (tid & 1) * 8;
    int br = tid >> 4, bc = (tid & 15) * 4;

    for (int k0 = 0; k0 < K; k0 += 16) {
        __syncthreads();
        {
            const float* ap = &A[(size_t)(bm0 + ar) * K + k0 + ac];
            float4 av0 = *(const float4*)ap;
            float4 av1 = *(const float4*)(ap + 4);
            if (USEVOL) {
                av0.x *= volp[k0 + ac + 0]; av0.y *= volp[k0 + ac + 1];
                av0.z *= volp[k0 + ac + 2]; av0.w *= volp[k0 + ac + 3];
                av1.x *= volp[k0 + ac + 4]; av1.y *= volp[k0 + ac + 5];
                av1.z *= volp[k0 + ac + 6]; av1.w *= volp[k0 + ac + 7];
            }
            float xs[8] = {av0.x, av0.y, av0.z, av0.w,
                           av1.x, av1.y, av1.z, av1.w};
#pragma unroll
            for (int j = 0; j < 8; j++) {
                unsigned hi, lo;
                split_tf32(xs[j], hi, lo);
                Abig[ac + j][ar] = hi;
                Asml[ac + j][ar] = lo;
            }
            const float* bp = &Bw[(size_t)(k0 + br) * N + bn0 + bc];
            float4 bv = *(const float4*)bp;
            if (BLO) {
                uint4 hb, lb;
                split_tf32(bv.x, hb.x, lb.x);
                split_tf32(bv.y, hb.y, lb.y);
                split_tf32(bv.z, hb.z, lb.z);
                split_tf32(bv.w, hb.w, lb.w);
                *(uint4*)&Bbig[br][bc] = hb;
                *(uint4*)&Bsml[br][bc] = lb;
            } else {
                uint4 hb;
                hb.x = cvt_tf32(bv.x); hb.y = cvt_tf32(bv.y);
                hb.z = cvt_tf32(bv.z); hb.w = cvt_tf32(bv.w);
                *(uint4*)&Bbig[br][bc] = hb;
            }
        }
        __syncthreads();

#pragma unroll
        for (int ks = 0; ks < 2; ks++) {
            int kb = ks * 8;
            unsigned ab[2][4], al[2][4];
#pragma unroll
            for (int mt = 0; mt < 2; mt++) {
                int m0 = wm + mt * 16 + g;
                ab[mt][0] = Abig[kb + tg    ][m0];
                ab[mt][1] = Abig[kb + tg    ][m0 + 8];
                ab[mt][2] = Abig[kb + tg + 4][m0];
                ab[mt][3] = Abig[kb + tg + 4][m0 + 8];
                al[mt][0] = Asml[kb + tg    ][m0];
                al[mt][1] = Asml[kb + tg    ][m0 + 8];
                al[mt][2] = Asml[kb + tg + 4][m0];
                al[mt][3] = Asml[kb + tg + 4][m0 + 8];
            }
            unsigned bb[4][2], bl[4][2];
#pragma unroll
            for (int nt = 0; nt < 4; nt++) {
                int n0 = wn + nt * 8 + g;
                bb[nt][0] = Bbig[kb + tg    ][n0];
                bb[nt][1] = Bbig[kb + tg + 4][n0];
                if (BLO) {
                    bl[nt][0] = Bsml[kb + tg    ][n0];
                    bl[nt][1] = Bsml[kb + tg + 4][n0];
                }
            }
#pragma unroll
            for (int mt = 0; mt < 2; mt++)
#pragma unroll
                for (int nt = 0; nt < 4; nt++) {
                    float* d = acc[mt][nt];
                    mma_tf32(d[0], d[1], d[2], d[3],
                             ab[mt][0], ab[mt][1], ab[mt][2], ab[mt][3],
                             bb[nt][0], bb[nt][1]);
                    mma_tf32(d[0], d[1], d[2], d[3],
                             al[mt][0], al[mt][1], al[mt][2], al[mt][3],
                             bb[nt][0], bb[nt][1]);
                    if (BLO)
                        mma_tf32(d[0], d[1], d[2], d[3],
                                 ab[mt][0], ab[mt][1], ab[mt][2], ab[mt][3],
                                 bl[nt][0], bl[nt][1]);
                }
        }
    }

#pragma unroll
    for (int mt = 0; mt < 2; mt++)
#pragma unroll
        for (int nt = 0; nt < 4; nt++) {
            int r0 = bm0 + wm + mt * 16 + g;
            int c0 = bn0 + wn + nt * 8 + tg * 2;
            float2 bi = *(const float2*)&bias[c0];
            float* p0 = &C[(size_t)r0 * N + c0];
            float* p1 = &C[(size_t)(r0 + 8) * N + c0];
            float2 v0, v1;
            v0.x = acc[mt][nt][0] + bi.x; v0.y = acc[mt][nt][1] + bi.y;
            v1.x = acc[mt][nt][2] + bi.x; v1.y = acc[mt][nt][3] + bi.y;
            if (ADD) {
                float2 o0 = *(float2*)p0, o1 = *(float2*)p1;
                v0.x += o0.x; v0.y += o0.y;
                v1.x += o1.x; v1.y += o1.y;
            }
            *(float2*)p0 = v0;
            *(float2*)p1 = v1;
        }
}

/* ------------------------------------------------------------------ */
/* ProbSparse attention, 16 queries per 512-thread block               */
/* phase 1 (QK^T) 3xTF32, phase 3 (AV) 1xTF32 (both sides hi-only)     */
/* ------------------------------------------------------------------ */
#define SC_PITCH  1032
#define SC_OFF    0
#define HIST_OFF  16512
#define QHI_OFF   20608
#define QLO_OFF   21184
#define RZ_OFF    21760
#define ATTN_SMEM (21776 * 4)

__device__ __forceinline__ unsigned f2u(float f) {
    unsigned u = __float_as_uint(f);
    return (u & 0x80000000u) ? ~u : (u | 0x80000000u);
}
__device__ __forceinline__ float u2f(unsigned x) {
    unsigned v = (x & 0x80000000u) ? (x ^ 0x80000000u) : ~x;
    return __uint_as_float(v);
}

__global__ void __launch_bounds__(512, 2)
attn_kernel(const float* __restrict__ QKV, float* __restrict__ O) {
    extern __shared__ float smx[];
    unsigned* scu  = (unsigned*)(smx + SC_OFF);   /* u32 scores -> fp32 weights */
    int*      histb = (int*)(smx + HIST_OFF);     /* later: AV partials */
    unsigned* Qhi  = (unsigned*)(smx + QHI_OFF);
    unsigned* Qlo  = (unsigned*)(smx + QLO_OFF);
    float*    rzs  = smx + RZ_OFF;

    int tid = threadIdx.x, lane = tid & 31, w = tid >> 5;
    int bh = blockIdx.y, b = bh >> 3, h = bh & 7;
    int qbase = blockIdx.x * 16;
    size_t tokbase = (size_t)b * LL;
    const float* base = QKV + tokbase * 768 + h * 32;

    /* stage Q tile as tf32 hi/lo: 16 x 32, pitch 36 */
    {
        int q = tid >> 5, d = tid & 31;
        float qv = base[(size_t)(qbase + q) * 768 + d];
        unsigned hi, lo;
        split_tf32(qv, hi, lo);
        Qhi[q * 36 + d] = hi;
        Qlo[q * 36 + d] = lo;
    }
    __syncthreads();

    int g = lane >> 2, tg = lane & 3;

    /* ---------------- phase 1: S = Q K^T via 3xTF32 mma ------------- */
    {
        unsigned ah[4][4], al[4][4];
#pragma unroll
        for (int s = 0; s < 4; s++) {
            int d0 = s * 8;
            ah[s][0] = Qhi[g * 36 + d0 + tg];
            ah[s][1] = Qhi[(g + 8) * 36 + d0 + tg];
            ah[s][2] = Qhi[g * 36 + d0 + tg + 4];
            ah[s][3] = Qhi[(g + 8) * 36 + d0 + tg + 4];
            al[s][0] = Qlo[g * 36 + d0 + tg];
            al[s][1] = Qlo[(g + 8) * 36 + d0 + tg];
            al[s][2] = Qlo[g * 36 + d0 + tg + 4];
            al[s][3] = Qlo[(g + 8) * 36 + d0 + tg + 4];
        }
        const unsigned* KH = g_KThi + (size_t)bh * 32 * LL;
        const unsigned* KL = g_KTlo + (size_t)bh * 32 * LL;
        int off0 = tg * LL + g;
        int off1 = (tg + 4) * LL + g;
#pragma unroll
        for (int kg = 0; kg < 8; kg++) {
            int kb = w * 64 + kg * 8;
            float c0 = 0.f, c1 = 0.f, c2 = 0.f, c3 = 0.f;
#pragma unroll
            for (int s = 0; s < 4; s++) {
                unsigned b0h = KH[s * 8 * LL + kb + off0];
                unsigned b1h = KH[s * 8 * LL + kb + off1];
                unsigned b0l = KL[s * 8 * LL + kb + off0];
                unsigned b1l = KL[s * 8 * LL + kb + off1];
                mma_tf32(c0, c1, c2, c3,
                         ah[s][0], ah[s][1], ah[s][2], ah[s][3], b0h, b1h);
                mma_tf32(c0, c1, c2, c3,
                         al[s][0], al[s][1], al[s][2], al[s][3], b0h, b1h);
                mma_tf32(c0, c1, c2, c3,
                         ah[s][0], ah[s][1], ah[s][2], ah[s][3], b0l, b1l);
            }
            int cc = kb + tg * 2;
            uint2 p0 = make_uint2(f2u(c0), f2u(c1));
            uint2 p1 = make_uint2(f2u(c2), f2u(c3));
            *(uint2*)&scu[g * SC_PITCH + cc]       = p0;
            *(uint2*)&scu[(g + 8) * SC_PITCH + cc] = p1;
        }
    }
    __syncthreads();

    unsigned* row = scu + w * SC_PITCH;
    const uint4* row4 = (const uint4*)row;

    /* -------- phase 2: exact 256-th largest (4-pass radix, u32) ----- */
    int* hw = histb + w * 256;
    unsigned prefix = 0, umax = 0;
    int krem = TOPK;
#pragma unroll
    for (int pass = 0; pass < 4; pass++) {
        int shift = 24 - 8 * pass;
        for (int i = lane; i < 256; i += 32) hw[i] = 0;
        __syncwarp();
        for (int j4 = lane; j4 < 256; j4 += 32) {
            uint4 s4 = row4[j4];
            if (pass == 0) {
                umax = max(max(umax, s4.x), max(s4.y, max(s4.z, s4.w)));
                atomicAdd(&hw[s4.x >> 24], 1);
                atomicAdd(&hw[s4.y >> 24], 1);
                atomicAdd(&hw[s4.z >> 24], 1);
                atomicAdd(&hw[s4.w >> 24], 1);
            } else {
                unsigned hi = (prefix >> shift) >> 8;
                if (((s4.x >> shift) >> 8) == hi) atomicAdd(&hw[(s4.x >> shift) & 255], 1);
                if (((s4.y >> shift) >> 8) == hi) atomicAdd(&hw[(s4.y >> shift) & 255], 1);
                if (((s4.z >> shift) >> 8) == hi) atomicAdd(&hw[(s4.z >> shift) & 255], 1);
                if (((s4.w >> shift) >> 8) == hi) atomicAdd(&hw[(s4.w >> shift) & 255], 1);
            }
        }
        __syncwarp();
        int gs = 0;
#pragma unroll
        for (int i = 0; i < 8; i++) gs += hw[255 - (lane * 8 + i)];
        int S = gs;
#pragma unroll
        for (int off = 1; off < 32; off <<= 1) {
            int t2 = __shfl_up_sync(0xffffffffu, S, off);
            if (lane >= off) S += t2;
        }
        unsigned bal = __ballot_sync(0xffffffffu, S >= krem);
        int L = __ffs(bal) - 1;
        int SL  = __shfl_sync(0xffffffffu, S, L);
        int gsL = __shfl_sync(0xffffffffu, gs, L);
        int c = SL - gsL, selbin = 255 - L * 8, knew = krem;
#pragma unroll
        for (int i = 0; i < 8; i++) {
            int bn = 255 - (L * 8 + i);
            int hv = hw[bn];
            c += hv;
            if (c >= krem) { selbin = bn; knew = krem - (c - hv); break; }
        }
        prefix |= ((unsigned)selbin) << shift;
        krem = knew;
    }
#pragma unroll
    for (int o = 16; o > 0; o >>= 1)
        umax = max(umax, __shfl_xor_sync(0xffffffffu, umax, o));
    float lmax = u2f(umax);
    unsigned thr = prefix;

    /* -------- softmax: dense weights written back over score row ---- */
    float zs = 0.f;
#pragma unroll
    for (int kt = 0; kt < 8; kt++) {
        uint4 s4 = row4[kt * 32 + lane];
        float w0 = (s4.x >= thr) ? __expf(u2f(s4.x) - lmax) : 0.f;
        float w1 = (s4.y >= thr) ? __expf(u2f(s4.y) - lmax) : 0.f;
        float w2 = (s4.z >= thr) ? __expf(u2f(s4.z) - lmax) : 0.f;
        float w3 = (s4.w >= thr) ? __expf(u2f(s4.w) - lmax) : 0.f;
        ((float4*)row)[kt * 32 + lane] = make_float4(w0, w1, w2, w3);
        zs += w0 + w1 + w2 + w3;
    }
#pragma unroll
    for (int o = 16; o > 0; o >>= 1) zs += __shfl_xor_sync(0xffffffffu, zs, o);
    if (lane == 0) rzs[w] = 1.f / zs;
    __syncthreads();   /* all weights + rz visible to all warps */

    /* -------- phase 3: O = W @ V via 1xTF32 mma (hi-only) ----------- */
    float av[4][4];
#pragma unroll
    for (int nt = 0; nt < 4; nt++)
#pragma unroll
        for (int i = 0; i < 4; i++) av[nt][i] = 0.f;
    {
        const float* scwf = (const float*)scu;
        const unsigned* VH = g_Vhi + ((size_t)bh * LL + w * 64) * 32;
#pragma unroll
        for (int s = 0; s < 8; s++) {
            int k = w * 64 + s * 8;
            unsigned a0h = cvt_tf32(scwf[g * SC_PITCH + k + tg]);
            unsigned a1h = cvt_tf32(scwf[(g + 8) * SC_PITCH + k + tg]);
            unsigned a2h = cvt_tf32(scwf[g * SC_PITCH + k + tg + 4]);
            unsigned a3h = cvt_tf32(scwf[(g + 8) * SC_PITCH + k + tg + 4]);
            int r0 = (s * 8 + tg) * 32;
            int r1 = (s * 8 + tg + 4) * 32;
#pragma unroll
            for (int nt = 0; nt < 4; nt++) {
                int c = nt * 8 + g;
                unsigned b0h = VH[r0 + c], b1h = VH[r1 + c];
                float* d = av[nt];
                mma_tf32(d[0], d[1], d[2], d[3], a0h, a1h, a2h, a3h, b0h, b1h);
            }
        }
    }

    /* -------- cross-warp reduction of AV partials (2 d-halves) ------ */
    float* P = smx + HIST_OFF;   /* 4096 floats; hist is dead */
#pragma unroll
    for (int hh = 0; hh < 2; hh++) {
        __syncthreads();
#pragma unroll
        for (int nt = hh * 2; nt < hh * 2 + 2; nt++) {
            int dl = (nt - hh * 2) * 8 + tg * 2;
            P[w * 256 + g * 16 + dl]           = av[nt][0];
            P[w * 256 + g * 16 + dl + 1]       = av[nt][1];
            P[w * 256 + (g + 8) * 16 + dl]     = av[nt][2];
            P[w * 256 + (g + 8) * 16 + dl + 1] = av[nt][3];
        }
        __syncthreads();
        if (tid < 256) {
            int q = tid >> 4, dl = tid & 15;
            float s = 0.f;
#pragma unroll
            for (int w2 = 0; w2 < 16; w2++) s += P[w2 * 256 + q * 16 + dl];
            O[(tokbase + qbase + q) * 256 + h * 32 + hh * 16 + dl] = s * rzs[q];
        }
    }
}

/* ------------------------------------------------------------------ */
/* Volatilite: vol[b,j] = std over L of F[b,:,j]                       */
/* ------------------------------------------------------------------ */
__global__ void vol_kernel(const float* __restrict__ F) {
    int tx = threadIdx.x & 127;
    int ty = threadIdx.x >> 7;
    int j = blockIdx.x * 128 + tx;
    int b = blockIdx.y;
    float s = 0.f, ss = 0.f;
    for (int l = ty; l < LL; l += 4) {
        float v = F[((size_t)(b * LL + l)) * DFF + j];
        s += v; ss += v * v;
    }
    __shared__ float sh1[4][128], sh2[4][128];
    sh1[ty][tx] = s; sh2[ty][tx] = ss;
    __syncthreads();
    if (ty == 0) {
        s  = sh1[0][tx] + sh1[1][tx] + sh1[2][tx] + sh1[3][tx];
        ss = sh2[0][tx] + sh2[1][tx] + sh2[2][tx] + sh2[3][tx];
        float mean = s * (1.f / LL);
        float var  = ss * (1.f / LL) - mean * mean;
        g_VOL[b * DFF + j] = sqrtf(fmaxf(var, 0.f));
    }
}

/* ------------------------------------------------------------------ */
extern "C" void kernel_launch(void* const* d_in, const int* in_sizes, int n_in,
                              void* d_out, int out_size) {
    const float* x     = (const float*)d_in[0];
    const float* in_w  = (const float*)d_in[1];
    const float* in_b  = (const float*)d_in[2];
    const float* ln1_g = (const float*)d_in[3];
    const float* ln1_b = (const float*)d_in[4];
    const float* qkv_w = (const float*)d_in[5];
    const float* qkv_b = (const float*)d_in[6];
    const float* out_w = (const float*)d_in[7];
    const float* out_b = (const float*)d_in[8];
    const float* lna_g = (const float*)d_in[9];
    const float* lna_b = (const float*)d_in[10];
    const float* ln2_g = (const float*)d_in[11];
    const float* ln2_b = (const float*)d_in[12];
    const float* ff1_w = (const float*)d_in[13];
    const float* ff1_b = (const float*)d_in[14];
    const float* ff2_w = (const float*)d_in[15];
    const float* ff2_b = (const float*)d_in[16];
    const float* lnf_g = (const float*)d_in[17];
    const float* lnf_b = (const float*)d_in[18];
    float* out = (float*)d_out;

    float *H, *S, *Q, *O, *P, *F;
    cudaGetSymbolAddress((void**)&H, g_H);
    cudaGetSymbolAddress((void**)&S, g_S);
    cudaGetSymbolAddress((void**)&Q, g_QKV);
    cudaGetSymbolAddress((void**)&O, g_O);
    cudaGetSymbolAddress((void**)&P, g_P);
    cudaGetSymbolAddress((void**)&F, g_F);

    cudaFuncSetAttribute((const void*)attn_kernel,
                         cudaFuncAttributeMaxDynamicSharedMemorySize, ATTN_SMEM);

    embed_kernel<<<TT, 256>>>(x, in_w, in_b);

    for (int layer = 0; layer < NLAY; layer++) {
        /* s2 = LN1(h) */
        ln_kernel<<<TT / 8, 256>>>(H, ln1_g, ln1_b, S);
        /* qkv = s2 @ qkv_w + qkv_b (full 3xTF32 — feeds top-k scores) */
        gemm_kernel<false, false, true><<<dim3(768 / 64, TT / 128), 256>>>(
            S, qkv_w, qkv_b, Q, TT, 768, DM);
        /* K -> tf32 hi/lo transposed, V -> tf32 hi native */
        kvconv_kernel<<<dim3(32, BB * NH), 256>>>();
        /* probsparse attention */
        attn_kernel<<<dim3(LL / 16, BB * NH), 512, ATTN_SMEM>>>(Q, O);
        /* P = O @ out_w + out_b (2-term) */
        gemm_kernel<false, false, false><<<dim3(256 / 64, TT / 128), 256>>>(
            O, out_w, out_b, P, TT, DM, DM);
        /* h += LN(P + s2);  s2 = LN2(h)   (fused) */
        lna_ln2_kernel<<<TT / 8, 256>>>(P, S, lna_g, lna_b, ln2_g, ln2_b, H);
        /* F = s2 @ ff1_w + ff1_b (2-term) */
        gemm_kernel<false, false, false><<<dim3(1024 / 64, TT / 128), 256>>>(
            S, ff1_w, ff1_b, F, TT, DFF, DM);
        /* vol[b,j] */
        vol_kernel<<<dim3(DFF / 128, BB), 512>>>(F);
        /* h += (F * vol) @ ff2_w + ff2_b (2-term) */
        gemm_kernel<true, true, false><<<dim3(256 / 64, TT / 128), 256>>>(
            F, ff2_w, ff2_b, H, TT, DM, DFF);
    }

    /* out = LN_f(h) */
    ln_kernel<<<TT / 8, 256>>>(H, lnf_g, lnf_b, out);
}